// round 1
// baseline (speedup 1.0000x reference)
#include <cuda_runtime.h>
#include <math.h>
#include <float.h>

#define NROW 16384
#define DIM  512
#define MARGIN 2.0f
#define EPSV 1e-6f

// ---- device scratch (no allocations allowed) ----
__device__ float g_sq[NROW];
__device__ int   g_neg[NROW];
__device__ float g_rowloss[NROW];

// ============================================================
// Kernel 1: per-row squared norms
// ============================================================
__global__ __launch_bounds__(128) void sq_kernel(const float* __restrict__ X) {
    int row = blockIdx.x;
    int t = threadIdx.x;
    const float* xr = X + (size_t)row * DIM;
    float s = 0.f;
#pragma unroll
    for (int i = 0; i < 4; ++i) {
        float v = xr[t + i * 128];
        s += v * v;
    }
#pragma unroll
    for (int o = 16; o > 0; o >>= 1) s += __shfl_down_sync(0xffffffffu, s, o);
    __shared__ float ws[4];
    if ((t & 31) == 0) ws[t >> 5] = s;
    __syncthreads();
    if (t == 0) g_sq[row] = ws[0] + ws[1] + ws[2] + ws[3];
}

// ============================================================
// Kernel 2: fused pairwise-distance GEMM + streaming top-3.
// BM=BN=128, BK=16, 256 threads (16x16), 8x8 microtile/thread.
// Each thread keeps a local top-3 per each of its 8 rows over the
// columns it touches; merged per-row at the end (lexicographic
// (val,idx) compare matches jax top_k tie-breaking).
// ============================================================
__global__ __launch_bounds__(256, 1) void dist_topk_kernel(const float* __restrict__ X) {
    __shared__ float As[16][128];
    __shared__ float Bs[16][128];
    __shared__ float mv[32][48];
    __shared__ int   mi[32][48];

    const int tid = threadIdx.x;
    const int tx = tid & 15;       // column group
    const int ty = tid >> 4;       // row group
    const int rowBase = blockIdx.x * 128;

    float tv[8][3];
    int   ti[8][3];
#pragma unroll
    for (int i = 0; i < 8; ++i)
#pragma unroll
        for (int q = 0; q < 3; ++q) { tv[i][q] = FLT_MAX; ti[i][q] = 0x7fffffff; }

    float sqr[8];
#pragma unroll
    for (int i = 0; i < 8; ++i) sqr[i] = g_sq[rowBase + ty * 8 + i];

    for (int jt = 0; jt < NROW / 128; ++jt) {
        const int colBase = jt * 128;

        float c[8][8];
#pragma unroll
        for (int i = 0; i < 8; ++i)
#pragma unroll
            for (int j = 0; j < 8; ++j) c[i][j] = 0.f;

        for (int kt = 0; kt < DIM; kt += 16) {
            __syncthreads();
            // load A tile (rows) + B tile (cols): 512 float4 each, 2/thread
#pragma unroll
            for (int l = 0; l < 2; ++l) {
                int f = tid + l * 256;
                int r = f >> 2;
                int kq = (f & 3) * 4;
                float4 va = *(const float4*)&X[(rowBase + r) * DIM + kt + kq];
                As[kq + 0][r] = va.x; As[kq + 1][r] = va.y;
                As[kq + 2][r] = va.z; As[kq + 3][r] = va.w;
                float4 vb = *(const float4*)&X[(colBase + r) * DIM + kt + kq];
                Bs[kq + 0][r] = vb.x; Bs[kq + 1][r] = vb.y;
                Bs[kq + 2][r] = vb.z; Bs[kq + 3][r] = vb.w;
            }
            __syncthreads();

#pragma unroll
            for (int kk = 0; kk < 16; ++kk) {
                float a[8], b[8];
                *(float4*)&a[0] = *(const float4*)&As[kk][ty * 8];
                *(float4*)&a[4] = *(const float4*)&As[kk][ty * 8 + 4];
                *(float4*)&b[0] = *(const float4*)&Bs[kk][tx * 8];
                *(float4*)&b[4] = *(const float4*)&Bs[kk][tx * 8 + 4];
#pragma unroll
                for (int i = 0; i < 8; ++i)
#pragma unroll
                    for (int j = 0; j < 8; ++j)
                        c[i][j] += a[i] * b[j];
            }
        }

        // epilogue: dist2 + top-3 insert
#pragma unroll
        for (int j = 0; j < 8; ++j) {
            int col = colBase + tx * 8 + j;
            float sqc = g_sq[col];
#pragma unroll
            for (int i = 0; i < 8; ++i) {
                float d2 = sqr[i] + sqc - 2.f * c[i][j];
                bool b2 = (d2 < tv[i][2]) || (d2 == tv[i][2] && col < ti[i][2]);
                if (b2) {
                    bool b1 = (d2 < tv[i][1]) || (d2 == tv[i][1] && col < ti[i][1]);
                    bool b0 = (d2 < tv[i][0]) || (d2 == tv[i][0] && col < ti[i][0]);
                    if (b0) {
                        tv[i][2] = tv[i][1]; ti[i][2] = ti[i][1];
                        tv[i][1] = tv[i][0]; ti[i][1] = ti[i][0];
                        tv[i][0] = d2;       ti[i][0] = col;
                    } else if (b1) {
                        tv[i][2] = tv[i][1]; ti[i][2] = ti[i][1];
                        tv[i][1] = d2;       ti[i][1] = col;
                    } else {
                        tv[i][2] = d2;       ti[i][2] = col;
                    }
                }
            }
        }
    }

    // ---- merge 16 per-thread candidate lists per row, 32 rows/chunk ----
    for (int base = 0; base < 128; base += 32) {
        __syncthreads();
        if (ty * 8 >= base && ty * 8 < base + 32) {
#pragma unroll
            for (int i = 0; i < 8; ++i) {
                int rl = ty * 8 + i - base;
#pragma unroll
                for (int q = 0; q < 3; ++q) {
                    mv[rl][tx * 3 + q] = tv[i][q];
                    mi[rl][tx * 3 + q] = ti[i][q];
                }
            }
        }
        __syncthreads();
        if (tid < 32) {
            float v0 = FLT_MAX, v1 = FLT_MAX, v2 = FLT_MAX;
            int   i0 = 0x7fffffff, i1 = 0x7fffffff, i2 = 0x7fffffff;
            for (int cnd = 0; cnd < 48; ++cnd) {
                float d = mv[tid][cnd];
                int   ix = mi[tid][cnd];
                bool b2 = (d < v2) || (d == v2 && ix < i2);
                if (b2) {
                    bool b1 = (d < v1) || (d == v1 && ix < i1);
                    bool b0 = (d < v0) || (d == v0 && ix < i0);
                    if (b0)      { v2 = v1; i2 = i1; v1 = v0; i1 = i0; v0 = d; i0 = ix; }
                    else if (b1) { v2 = v1; i2 = i1; v1 = d; i1 = ix; }
                    else         { v2 = d;  i2 = ix; }
                }
            }
            g_neg[rowBase + base + tid] = i2;
        }
    }
}

// ============================================================
// Kernel 3: per-row triplet loss (one warp per row)
// ============================================================
__global__ __launch_bounds__(256) void rowloss_kernel(const float* __restrict__ X,
                                                      const float* __restrict__ P) {
    int warp = threadIdx.x >> 5;
    int lane = threadIdx.x & 31;
    int row = blockIdx.x * 8 + warp;
    const float4* xr = (const float4*)(X + (size_t)row * DIM);
    const float4* pr = (const float4*)(P + (size_t)row * DIM);
    const float4* nr = (const float4*)(X + (size_t)g_neg[row] * DIM);
    float sap = 0.f, san = 0.f;
#pragma unroll
    for (int i = 0; i < 4; ++i) {
        float4 x = xr[lane + 32 * i];
        float4 p = pr[lane + 32 * i];
        float4 v = nr[lane + 32 * i];
        float d;
        d = x.x - p.x + EPSV; sap += d * d;
        d = x.y - p.y + EPSV; sap += d * d;
        d = x.z - p.z + EPSV; sap += d * d;
        d = x.w - p.w + EPSV; sap += d * d;
        d = x.x - v.x + EPSV; san += d * d;
        d = x.y - v.y + EPSV; san += d * d;
        d = x.z - v.z + EPSV; san += d * d;
        d = x.w - v.w + EPSV; san += d * d;
    }
#pragma unroll
    for (int o = 16; o > 0; o >>= 1) {
        sap += __shfl_down_sync(0xffffffffu, sap, o);
        san += __shfl_down_sync(0xffffffffu, san, o);
    }
    if (lane == 0)
        g_rowloss[row] = fmaxf(sqrtf(sap) - sqrtf(san) + MARGIN, 0.f);
}

// ============================================================
// Kernel 4: mean reduction -> d_out[0]
// ============================================================
__global__ __launch_bounds__(512) void reduce_kernel(float* __restrict__ out) {
    int t = threadIdx.x;
    float s = 0.f;
    for (int i = t; i < NROW; i += 512) s += g_rowloss[i];
#pragma unroll
    for (int o = 16; o > 0; o >>= 1) s += __shfl_down_sync(0xffffffffu, s, o);
    __shared__ float ws[16];
    if ((t & 31) == 0) ws[t >> 5] = s;
    __syncthreads();
    if (t == 0) {
        float tot = 0.f;
#pragma unroll
        for (int w = 0; w < 16; ++w) tot += ws[w];
        out[0] = tot / (float)NROW;
    }
}

extern "C" void kernel_launch(void* const* d_in, const int* in_sizes, int n_in,
                              void* d_out, int out_size) {
    const float* X = (const float*)d_in[0];   // inputs  [16384, 512] f32
    const float* P = (const float*)d_in[1];   // positive[16384, 512] f32
    float* out = (float*)d_out;

    sq_kernel<<<NROW, 128>>>(X);
    dist_topk_kernel<<<NROW / 128, 256>>>(X);
    rowloss_kernel<<<NROW / 8, 256>>>(X, P);
    reduce_kernel<<<1, 512>>>(out);
}

// round 3
// speedup vs baseline: 8.8834x; 8.8834x over previous
#include <cuda_runtime.h>
#include <cuda_bf16.h>
#include <math.h>
#include <float.h>
#include <stdint.h>

#define NROW 16384
#define DIM  512
#define MARGIN 2.0f
#define EPSV 1e-6f

// Arch-specific (sm_103a) feature gate: tcgen05/TMEM PTX only exists in the
// 'a' compilation pass. The plain compute_103/sm_103 pass gets a SIMT fallback.
#if defined(__CUDA_ARCH_FEAT_SM103_ALL) || (defined(__CUDA_ARCH_SPECIFIC__) && (__CUDA_ARCH_SPECIFIC__ == 1030))
#define HAS_TCGEN05 1
#else
#define HAS_TCGEN05 0
#endif

// ---- device scratch (no dynamic allocation allowed) ----
__device__ float g_sq[NROW];
__device__ int   g_neg[NROW];
__device__ float g_rowloss[NROW];
__device__ __align__(16) uint32_t g_xb[NROW * DIM / 2];   // bf16x2-packed inputs

// SMEM layout (dynamic), tcgen05 path
#define SMEM_TPTR 0
#define SMEM_MBAR 8
#define SMEM_SQS  16          // 2 x 128 floats (double-buffered sq tile)
#define SMEM_B    2048        // 8 slabs x 16KB = 128KB
#define SMEM_TOTAL (2048 + 131072)

#define TMEM_A 0              // 256 cols: A 128x512 bf16
#define TMEM_D 256            // 128 cols: D 128x128 f32

#if HAS_TCGEN05
// ============================================================
// PTX helpers (sm_103a tcgen05 / mbarrier) — 'a'-pass only
// ============================================================
__device__ __forceinline__ uint32_t elect_one() {
    uint32_t p;
    asm volatile("{\n\t.reg .pred p;\n\telect.sync _|p, 0xFFFFFFFF;\n\tselp.b32 %0, 1, 0, p;\n\t}" : "=r"(p));
    return p;
}
#define TCGEN05_ALLOC(dst, n) \
    asm volatile("tcgen05.alloc.cta_group::1.sync.aligned.shared::cta.b32 [%0], %1;" :: "r"(dst), "r"(n) : "memory")
#define TCGEN05_DEALLOC(t, n) \
    asm volatile("tcgen05.dealloc.cta_group::1.sync.aligned.b32 %0, %1;" :: "r"(t), "r"(n))
#define TCGEN05_RELINQ() \
    asm volatile("tcgen05.relinquish_alloc_permit.cta_group::1.sync.aligned;")
#define TCGEN05_WAIT_ST() asm volatile("tcgen05.wait::st.sync.aligned;" ::: "memory")
#define TCGEN05_WAIT_LD() asm volatile("tcgen05.wait::ld.sync.aligned;" ::: "memory")
#define TCGEN05_FENCE_BEFORE() asm volatile("tcgen05.fence::before_thread_sync;" ::: "memory")
#define TCGEN05_FENCE_AFTER()  asm volatile("tcgen05.fence::after_thread_sync;" ::: "memory")
#define FENCE_PROXY_ASYNC() asm volatile("fence.proxy.async.shared::cta;" ::: "memory")
#define MBARRIER_INIT(m, c) \
    asm volatile("mbarrier.init.shared.b64 [%0], %1;" :: "r"(m), "r"(c) : "memory")
#define TCGEN05_COMMIT(m) \
    asm volatile("tcgen05.commit.cta_group::1.mbarrier::arrive::one.shared::cluster.b64 [%0];" :: "r"(m) : "memory")

#define MBARRIER_WAIT_PARITY(mbar_smem_addr, phase_parity) do { \
    uint32_t _mbar = (uint32_t)(mbar_smem_addr); \
    uint32_t _parity = (uint32_t)(phase_parity); \
    uint32_t _done; \
    asm volatile("{\n\t.reg .pred p;\n\t" \
        "mbarrier.try_wait.parity.acquire.cta.shared::cta.b64 p, [%1], %2;\n\t" \
        "selp.b32 %0, 1, 0, p;\n\t}" : "=r"(_done) : "r"(_mbar), "r"(_parity) : "memory"); \
    if (!_done) { \
        asm volatile("{\n\t.reg .pred P1;\n\t" \
            "WAIT_LOOP_%=:\n\t" \
            "mbarrier.try_wait.parity.acquire.cta.shared::cta.b64 P1, [%0], %1, 0x989680;\n\t" \
            "@P1 bra.uni WAIT_DONE_%=;\n\t" \
            "bra.uni WAIT_LOOP_%=;\n\t" \
            "WAIT_DONE_%=:\n\t}" :: "r"(_mbar), "r"(_parity) : "memory"); \
    } \
} while (0)

#define TCGEN05_ST_X32(tmem_addr, r) \
    asm volatile("tcgen05.st.sync.aligned.32x32b.x32.b32 [%0], " \
        "{%1, %2, %3, %4, %5, %6, %7, %8, %9, %10, %11, %12, %13, %14, %15, %16, " \
        "%17, %18, %19, %20, %21, %22, %23, %24, %25, %26, %27, %28, %29, %30, %31, %32};" \
        :: "r"(tmem_addr), \
           "r"((r)[0]),"r"((r)[1]),"r"((r)[2]),"r"((r)[3]),"r"((r)[4]),"r"((r)[5]),"r"((r)[6]),"r"((r)[7]), \
           "r"((r)[8]),"r"((r)[9]),"r"((r)[10]),"r"((r)[11]),"r"((r)[12]),"r"((r)[13]),"r"((r)[14]),"r"((r)[15]), \
           "r"((r)[16]),"r"((r)[17]),"r"((r)[18]),"r"((r)[19]),"r"((r)[20]),"r"((r)[21]),"r"((r)[22]),"r"((r)[23]), \
           "r"((r)[24]),"r"((r)[25]),"r"((r)[26]),"r"((r)[27]),"r"((r)[28]),"r"((r)[29]),"r"((r)[30]),"r"((r)[31]) \
        : "memory")

#define TCGEN05_LD_X32(r, tmem_addr) \
    asm volatile("tcgen05.ld.sync.aligned.32x32b.x32.b32 " \
        "{%0, %1, %2, %3, %4, %5, %6, %7, %8, %9, %10, %11, %12, %13, %14, %15, " \
        "%16, %17, %18, %19, %20, %21, %22, %23, %24, %25, %26, %27, %28, %29, %30, %31}, [%32];" \
        : "=r"((r)[0]),"=r"((r)[1]),"=r"((r)[2]),"=r"((r)[3]),"=r"((r)[4]),"=r"((r)[5]),"=r"((r)[6]),"=r"((r)[7]), \
          "=r"((r)[8]),"=r"((r)[9]),"=r"((r)[10]),"=r"((r)[11]),"=r"((r)[12]),"=r"((r)[13]),"=r"((r)[14]),"=r"((r)[15]), \
          "=r"((r)[16]),"=r"((r)[17]),"=r"((r)[18]),"=r"((r)[19]),"=r"((r)[20]),"=r"((r)[21]),"=r"((r)[22]),"=r"((r)[23]), \
          "=r"((r)[24]),"=r"((r)[25]),"=r"((r)[26]),"=r"((r)[27]),"=r"((r)[28]),"=r"((r)[29]),"=r"((r)[30]),"=r"((r)[31]) \
        : "r"(tmem_addr))

// TS-mode bf16 MMA: A in TMEM, B via SMEM descriptor
__device__ __forceinline__ void mma_f16_ts(uint32_t d_tmem, uint32_t a_tmem,
                                           uint64_t b_desc, uint32_t idesc, bool acc) {
    uint32_t en = acc ? 1u : 0u;
    uint32_t z = 0u;
    asm volatile("{\n\t.reg .pred p;\n\tsetp.ne.u32 p, %5, 0;\n\t"
        "tcgen05.mma.cta_group::1.kind::f16 [%0], [%1], %2, %3, {%4, %4, %4, %4}, p;\n\t}"
        :: "r"(d_tmem), "r"(a_tmem), "l"(b_desc), "r"(idesc), "r"(z), "r"(en)
        : "memory");
}

// SW128 K-major SMEM descriptor (LBO=1, SBO=64)
__device__ __forceinline__ uint64_t make_desc(uint32_t addr) {
    return (uint64_t(2) << 61) | (uint64_t(1) << 46) | (uint64_t(64) << 32)
         | (uint64_t(1) << 16) | ((addr >> 4) & 0x3FFF);
}

// idesc: F32 accum, bf16 A/B, M=128 (8<<24), N=128 (16<<17)
#define MMA_IDESC ((8u << 24) | (16u << 17) | (1u << 10) | (1u << 7) | (1u << 4))
#endif  // HAS_TCGEN05

__device__ __forceinline__ uint32_t smem_u32(const void* p) {
    uint32_t a;
    asm("{ .reg .u64 t; cvta.to.shared.u64 t, %1; cvt.u32.u64 %0, t; }" : "=r"(a) : "l"(p));
    return a;
}

// ============================================================
// Kernel 0: fp32 -> packed bf16x2 convert
// ============================================================
__global__ __launch_bounds__(256) void cvt_kernel(const float* __restrict__ X) {
    size_t i = ((size_t)blockIdx.x * 256 + threadIdx.x) * 4;
    float4 v = *(const float4*)(X + i);
    uint32_t lo, hi;
    asm("cvt.rn.bf16x2.f32 %0, %1, %2;" : "=r"(lo) : "f"(v.y), "f"(v.x));
    asm("cvt.rn.bf16x2.f32 %0, %1, %2;" : "=r"(hi) : "f"(v.w), "f"(v.z));
    *(uint2*)(g_xb + i / 2) = make_uint2(lo, hi);
}

// ============================================================
// Kernel 1: per-row squared norms (fp32, exact)
// ============================================================
__global__ __launch_bounds__(128) void sq_kernel(const float* __restrict__ X) {
    int row = blockIdx.x;
    int t = threadIdx.x;
    const float* xr = X + (size_t)row * DIM;
    float s = 0.f;
#pragma unroll
    for (int i = 0; i < 4; ++i) { float v = xr[t + i * 128]; s += v * v; }
#pragma unroll
    for (int o = 16; o > 0; o >>= 1) s += __shfl_down_sync(0xffffffffu, s, o);
    __shared__ float ws[4];
    if ((t & 31) == 0) ws[t >> 5] = s;
    __syncthreads();
    if (t == 0) g_sq[row] = ws[0] + ws[1] + ws[2] + ws[3];
}

// ============================================================
// Kernel 2: GEMM + streaming top-3 (3rd NN index).
// sm_103a pass: tcgen05 bf16 TS-mode, A in TMEM, B in SW128 SMEM.
// non-'a' pass: SIMT bf16 fallback (never selected on GB300 if the
// sm_103a cubin exists; keeps every ptxas pass compiling).
// 128 CTAs x 128 threads, rowBase = blockIdx.x * 128.
// key = sq[j] - 2*dot(i,j) (rank-equivalent to dist2).
// ============================================================
__global__ __launch_bounds__(128, 1)
void mma_topk_kernel() {
    extern __shared__ char smem[];
    const uint32_t smem_base = smem_u32(smem);
    const int tid = threadIdx.x;
    const int rowBase = blockIdx.x * 128;
    const uint4* xb4 = (const uint4*)g_xb;

#if HAS_TCGEN05
    const int wid = tid >> 5;
    float* sqs = (float*)(smem + SMEM_SQS);

    // ---- TMEM alloc ----
    if (wid == 0) {
        TCGEN05_ALLOC(smem_base + SMEM_TPTR, 512);
        TCGEN05_RELINQ();
    }
    if (tid == 0) MBARRIER_INIT(smem_base + SMEM_MBAR, 1);
    __syncthreads();
    uint32_t tmem_base;
    asm volatile("ld.shared.b32 %0, [%1];" : "=r"(tmem_base) : "r"(smem_base + SMEM_TPTR));

    // ---- store A (this CTA's 128 rows x 512 K bf16) to TMEM ----
    {
        const uint4* arow = xb4 + (size_t)(rowBase + tid) * (DIM / 8);
        uint32_t wo = (uint32_t)(tid >> 5) << 21;
#pragma unroll
        for (int c8 = 0; c8 < 8; ++c8) {
            uint32_t r[32];
#pragma unroll
            for (int u = 0; u < 8; ++u) {
                uint4 v = arow[c8 * 8 + u];
                r[u * 4 + 0] = v.x; r[u * 4 + 1] = v.y;
                r[u * 4 + 2] = v.z; r[u * 4 + 3] = v.w;
            }
            TCGEN05_ST_X32(tmem_base + TMEM_A + c8 * 32 + wo, r);
        }
        TCGEN05_WAIT_ST();
    }

    // ---- prologue: B tile 0 + sq tile 0 ----
    {
        sqs[tid] = g_sq[tid];
#pragma unroll 8
        for (int l = 0; l < 64; ++l) {
            int f = tid + l * 128;
            int s = f >> 10, g = f & 1023, j = g >> 3, u = g & 7;
            uint4 v = xb4[(size_t)j * 64 + s * 8 + u];
            uint32_t bo = (uint32_t)(j * 128 + u * 16);
            uint32_t sw = bo ^ ((bo >> 3) & 0x70);
            *(uint4*)(smem + SMEM_B + s * 16384 + sw) = v;
        }
        FENCE_PROXY_ASYNC();
    }
    __syncthreads();

    const uint64_t bdesc0 = make_desc(smem_base + SMEM_B);

    float v0 = FLT_MAX, v1 = FLT_MAX, v2 = FLT_MAX;
    int   i0 = 0, i1 = 0, i2 = 0;

    for (int jt = 0; jt < NROW / 128; ++jt) {
        if (wid == 0) {
            if (elect_one()) {
#pragma unroll
                for (int c = 0; c < 32; ++c) {
                    uint64_t bd = bdesc0 + (uint64_t)((c >> 2) * 1024 + (c & 3) * 2);
                    mma_f16_ts(tmem_base + TMEM_D, tmem_base + TMEM_A + c * 8,
                               bd, MMA_IDESC, c > 0);
                }
                TCGEN05_COMMIT(smem_base + SMEM_MBAR);
            }
        }

        MBARRIER_WAIT_PARITY(smem_base + SMEM_MBAR, jt & 1);
        TCGEN05_FENCE_AFTER();

        // prefetch next B tile + sq tile (MMA done reading B)
        if (jt + 1 < NROW / 128) {
            int colB = (jt + 1) * 128;
            sqs[((jt + 1) & 1) * 128 + tid] = g_sq[colB + tid];
#pragma unroll 8
            for (int l = 0; l < 64; ++l) {
                int f = tid + l * 128;
                int s = f >> 10, g = f & 1023, j = g >> 3, u = g & 7;
                uint4 v = xb4[(size_t)(colB + j) * 64 + s * 8 + u];
                uint32_t bo = (uint32_t)(j * 128 + u * 16);
                uint32_t sw = bo ^ ((bo >> 3) & 0x70);
                *(uint4*)(smem + SMEM_B + s * 16384 + sw) = v;
            }
        }

        // epilogue: read D, update top-3
        const float* sqt = sqs + (jt & 1) * 128;
        const int colBase = jt * 128;
#pragma unroll
        for (int ch = 0; ch < 4; ++ch) {
            uint32_t dr[32];
            TCGEN05_LD_X32(dr, tmem_base + TMEM_D + ch * 32);
            TCGEN05_WAIT_LD();
#pragma unroll
            for (int c = 0; c < 32; ++c) {
                float key = fmaf(-2.f, __uint_as_float(dr[c]), sqt[ch * 32 + c]);
                int col = colBase + ch * 32 + c;
                if (key < v2) {
                    if (key < v1) {
                        v2 = v1; i2 = i1;
                        if (key < v0) { v1 = v0; i1 = i0; v0 = key; i0 = col; }
                        else          { v1 = key; i1 = col; }
                    } else { v2 = key; i2 = col; }
                }
            }
        }
        TCGEN05_FENCE_BEFORE();
        FENCE_PROXY_ASYNC();
        __syncthreads();
    }

    g_neg[rowBase + tid] = i2;

    __syncthreads();
    if (wid == 0) TCGEN05_DEALLOC(tmem_base, 512);

#else  // ---------------- SIMT fallback (non-'a' pass) ----------------
    // 128 threads as 16(tx) x 8(ty); two 64-row halves; BK=16; 8x8 microtiles.
    float* As = (float*)(smem);               // [16][64]
    float* Bs = (float*)(smem + 4096);        // [16][128]
    float* mv = (float*)(smem + 12288);       // [64][48]
    int*   mi = (int*)(smem + 36864);         // [64][48]
    const int tx = tid & 15, ty = tid >> 4;

    for (int half = 0; half < 2; ++half) {
        const int rh = rowBase + half * 64;
        float tv[8][3]; int tii[8][3];
#pragma unroll
        for (int i = 0; i < 8; ++i)
#pragma unroll
            for (int q = 0; q < 3; ++q) { tv[i][q] = FLT_MAX; tii[i][q] = 0x7fffffff; }

        for (int jt = 0; jt < NROW / 128; ++jt) {
            const int colBase = jt * 128;
            float c[8][8];
#pragma unroll
            for (int i = 0; i < 8; ++i)
#pragma unroll
                for (int j = 0; j < 8; ++j) c[i][j] = 0.f;

            for (int kt = 0; kt < DIM; kt += 16) {
                __syncthreads();
#pragma unroll
                for (int l = 0; l < 4; ++l) {           // As: 512 words
                    int f = tid + l * 128;
                    int r = f >> 3, u = f & 7;
                    uint32_t w = g_xb[(size_t)(rh + r) * 256 + kt / 2 + u];
                    __nv_bfloat162 b2 = *(__nv_bfloat162*)&w;
                    float2 f2 = __bfloat1622float2(b2);
                    As[(2 * u + 0) * 64 + r] = f2.x;
                    As[(2 * u + 1) * 64 + r] = f2.y;
                }
#pragma unroll
                for (int l = 0; l < 8; ++l) {           // Bs: 1024 words
                    int f = tid + l * 128;
                    int r = f >> 3, u = f & 7;
                    uint32_t w = g_xb[(size_t)(colBase + r) * 256 + kt / 2 + u];
                    __nv_bfloat162 b2 = *(__nv_bfloat162*)&w;
                    float2 f2 = __bfloat1622float2(b2);
                    Bs[(2 * u + 0) * 128 + r] = f2.x;
                    Bs[(2 * u + 1) * 128 + r] = f2.y;
                }
                __syncthreads();
#pragma unroll
                for (int kk = 0; kk < 16; ++kk) {
                    float a[8], b[8];
#pragma unroll
                    for (int i = 0; i < 8; ++i) a[i] = As[kk * 64 + ty * 8 + i];
#pragma unroll
                    for (int j = 0; j < 8; ++j) b[j] = Bs[kk * 128 + tx * 8 + j];
#pragma unroll
                    for (int i = 0; i < 8; ++i)
#pragma unroll
                        for (int j = 0; j < 8; ++j) c[i][j] += a[i] * b[j];
                }
            }
#pragma unroll
            for (int j = 0; j < 8; ++j) {
                int col = colBase + tx * 8 + j;
                float sqc = g_sq[col];
#pragma unroll
                for (int i = 0; i < 8; ++i) {
                    float d2 = fmaf(-2.f, c[i][j], sqc);
                    bool b2c = (d2 < tv[i][2]) || (d2 == tv[i][2] && col < tii[i][2]);
                    if (b2c) {
                        bool b1c = (d2 < tv[i][1]) || (d2 == tv[i][1] && col < tii[i][1]);
                        bool b0c = (d2 < tv[i][0]) || (d2 == tv[i][0] && col < tii[i][0]);
                        if (b0c) {
                            tv[i][2] = tv[i][1]; tii[i][2] = tii[i][1];
                            tv[i][1] = tv[i][0]; tii[i][1] = tii[i][0];
                            tv[i][0] = d2;       tii[i][0] = col;
                        } else if (b1c) {
                            tv[i][2] = tv[i][1]; tii[i][2] = tii[i][1];
                            tv[i][1] = d2;       tii[i][1] = col;
                        } else { tv[i][2] = d2; tii[i][2] = col; }
                    }
                }
            }
        }

        __syncthreads();
#pragma unroll
        for (int i = 0; i < 8; ++i)
#pragma unroll
            for (int q = 0; q < 3; ++q) {
                mv[(ty * 8 + i) * 48 + tx * 3 + q] = tv[i][q];
                mi[(ty * 8 + i) * 48 + tx * 3 + q] = tii[i][q];
            }
        __syncthreads();
        if (tid < 64) {
            float w0 = FLT_MAX, w1 = FLT_MAX, w2 = FLT_MAX;
            int   j0 = 0x7fffffff, j1 = 0x7fffffff, j2 = 0x7fffffff;
            for (int cnd = 0; cnd < 48; ++cnd) {
                float d = mv[tid * 48 + cnd];
                int   ix = mi[tid * 48 + cnd];
                bool b2c = (d < w2) || (d == w2 && ix < j2);
                if (b2c) {
                    bool b1c = (d < w1) || (d == w1 && ix < j1);
                    bool b0c = (d < w0) || (d == w0 && ix < j0);
                    if (b0c)      { w2 = w1; j2 = j1; w1 = w0; j1 = j0; w0 = d; j0 = ix; }
                    else if (b1c) { w2 = w1; j2 = j1; w1 = d; j1 = ix; }
                    else          { w2 = d;  j2 = ix; }
                }
            }
            g_neg[rh + tid] = j2;
        }
        __syncthreads();
    }
#endif
}

// ============================================================
// Kernel 3: per-row triplet loss (one warp per row, fp32 exact)
// ============================================================
__global__ __launch_bounds__(256) void rowloss_kernel(const float* __restrict__ X,
                                                      const float* __restrict__ P) {
    int warp = threadIdx.x >> 5;
    int lane = threadIdx.x & 31;
    int row = blockIdx.x * 8 + warp;
    const float4* xr = (const float4*)(X + (size_t)row * DIM);
    const float4* pr = (const float4*)(P + (size_t)row * DIM);
    const float4* nr = (const float4*)(X + (size_t)g_neg[row] * DIM);
    float sap = 0.f, san = 0.f;
#pragma unroll
    for (int i = 0; i < 4; ++i) {
        float4 x = xr[lane + 32 * i];
        float4 p = pr[lane + 32 * i];
        float4 v = nr[lane + 32 * i];
        float d;
        d = x.x - p.x + EPSV; sap += d * d;
        d = x.y - p.y + EPSV; sap += d * d;
        d = x.z - p.z + EPSV; sap += d * d;
        d = x.w - p.w + EPSV; sap += d * d;
        d = x.x - v.x + EPSV; san += d * d;
        d = x.y - v.y + EPSV; san += d * d;
        d = x.z - v.z + EPSV; san += d * d;
        d = x.w - v.w + EPSV; san += d * d;
    }
#pragma unroll
    for (int o = 16; o > 0; o >>= 1) {
        sap += __shfl_down_sync(0xffffffffu, sap, o);
        san += __shfl_down_sync(0xffffffffu, san, o);
    }
    if (lane == 0)
        g_rowloss[row] = fmaxf(sqrtf(sap) - sqrtf(san) + MARGIN, 0.f);
}

// ============================================================
// Kernel 4: mean reduction -> d_out[0]
// ============================================================
__global__ __launch_bounds__(512) void reduce_kernel(float* __restrict__ out) {
    int t = threadIdx.x;
    float s = 0.f;
    for (int i = t; i < NROW; i += 512) s += g_rowloss[i];
#pragma unroll
    for (int o = 16; o > 0; o >>= 1) s += __shfl_down_sync(0xffffffffu, s, o);
    __shared__ float ws[16];
    if ((t & 31) == 0) ws[t >> 5] = s;
    __syncthreads();
    if (t == 0) {
        float tot = 0.f;
#pragma unroll
        for (int w = 0; w < 16; ++w) tot += ws[w];
        out[0] = tot / (float)NROW;
    }
}

extern "C" void kernel_launch(void* const* d_in, const int* in_sizes, int n_in,
                              void* d_out, int out_size) {
    const float* X = (const float*)d_in[0];   // inputs  [16384, 512] f32
    const float* P = (const float*)d_in[1];   // positive[16384, 512] f32
    float* out = (float*)d_out;

    cudaFuncSetAttribute(mma_topk_kernel,
                         cudaFuncAttributeMaxDynamicSharedMemorySize, SMEM_TOTAL);

    cvt_kernel<<<NROW * DIM / (256 * 4), 256>>>(X);
    sq_kernel<<<NROW, 128>>>(X);
    mma_topk_kernel<<<128, 128, SMEM_TOTAL>>>();
    rowloss_kernel<<<NROW / 8, 256>>>(X, P);
    reduce_kernel<<<1, 512>>>(out);
}

// round 4
// speedup vs baseline: 16.3624x; 1.8419x over previous
#include <cuda_runtime.h>
#include <cuda_bf16.h>
#include <math.h>
#include <float.h>
#include <stdint.h>

#define NROW 16384
#define DIM  512
#define MARGIN 2.0f
#define EPSV 1e-6f

// Arch-specific (sm_103a) feature gate: tcgen05/TMEM PTX only exists in the
// 'a' compilation pass. The plain compute_103/sm_103 pass gets a SIMT fallback.
#if defined(__CUDA_ARCH_FEAT_SM103_ALL) || (defined(__CUDA_ARCH_SPECIFIC__) && (__CUDA_ARCH_SPECIFIC__ == 1030))
#define HAS_TCGEN05 1
#else
#define HAS_TCGEN05 0
#endif

// ---- device scratch (no dynamic allocation allowed) ----
__device__ float g_sq[NROW];
__device__ int   g_neg[NROW];
__device__ float g_rowloss[NROW];
__device__ __align__(16) uint32_t g_xb[NROW * DIM / 2];   // bf16x2-packed inputs

// SMEM layout (dynamic), tcgen05 path
#define SMEM_TPTR  0
#define SMEM_MBAR0 8
#define SMEM_MBAR1 16
#define SMEM_SQS   32            // 4 slots x 256B
#define SMEM_B     2048          // 2 x 65536 (N=64 tile: 64 rows x 512 K bf16)
#define SMEM_TOTAL (2048 + 131072)

#define TMEM_A  0                // 256 cols: A 128x512 bf16
#define TMEM_D0 256              // 64 cols: D 128x64 f32
#define TMEM_D1 320

#define NTILE 256                // 16384 / 64 column tiles

#if HAS_TCGEN05
// ============================================================
// PTX helpers (sm_103a tcgen05 / mbarrier / cp.async)
// ============================================================
__device__ __forceinline__ uint32_t elect_one() {
    uint32_t p;
    asm volatile("{\n\t.reg .pred p;\n\telect.sync _|p, 0xFFFFFFFF;\n\tselp.b32 %0, 1, 0, p;\n\t}" : "=r"(p));
    return p;
}
#define TCGEN05_ALLOC(dst, n) \
    asm volatile("tcgen05.alloc.cta_group::1.sync.aligned.shared::cta.b32 [%0], %1;" :: "r"(dst), "r"(n) : "memory")
#define TCGEN05_DEALLOC(t, n) \
    asm volatile("tcgen05.dealloc.cta_group::1.sync.aligned.b32 %0, %1;" :: "r"(t), "r"(n))
#define TCGEN05_RELINQ() \
    asm volatile("tcgen05.relinquish_alloc_permit.cta_group::1.sync.aligned;")
#define TCGEN05_WAIT_ST() asm volatile("tcgen05.wait::st.sync.aligned;" ::: "memory")
#define TCGEN05_WAIT_LD() asm volatile("tcgen05.wait::ld.sync.aligned;" ::: "memory")
#define TCGEN05_FENCE_BEFORE() asm volatile("tcgen05.fence::before_thread_sync;" ::: "memory")
#define TCGEN05_FENCE_AFTER()  asm volatile("tcgen05.fence::after_thread_sync;" ::: "memory")
#define FENCE_PROXY_ASYNC() asm volatile("fence.proxy.async.shared::cta;" ::: "memory")
#define MBARRIER_INIT(m, c) \
    asm volatile("mbarrier.init.shared.b64 [%0], %1;" :: "r"(m), "r"(c) : "memory")
#define TCGEN05_COMMIT(m) \
    asm volatile("tcgen05.commit.cta_group::1.mbarrier::arrive::one.shared::cluster.b64 [%0];" :: "r"(m) : "memory")

#define MBARRIER_WAIT_PARITY(mbar_smem_addr, phase_parity) do { \
    uint32_t _mbar = (uint32_t)(mbar_smem_addr); \
    uint32_t _parity = (uint32_t)(phase_parity); \
    uint32_t _done; \
    asm volatile("{\n\t.reg .pred p;\n\t" \
        "mbarrier.try_wait.parity.acquire.cta.shared::cta.b64 p, [%1], %2;\n\t" \
        "selp.b32 %0, 1, 0, p;\n\t}" : "=r"(_done) : "r"(_mbar), "r"(_parity) : "memory"); \
    if (!_done) { \
        asm volatile("{\n\t.reg .pred P1;\n\t" \
            "WAIT_LOOP_%=:\n\t" \
            "mbarrier.try_wait.parity.acquire.cta.shared::cta.b64 P1, [%0], %1, 0x989680;\n\t" \
            "@P1 bra.uni WAIT_DONE_%=;\n\t" \
            "bra.uni WAIT_LOOP_%=;\n\t" \
            "WAIT_DONE_%=:\n\t}" :: "r"(_mbar), "r"(_parity) : "memory"); \
    } \
} while (0)

#define TCGEN05_ST_X32(tmem_addr, r) \
    asm volatile("tcgen05.st.sync.aligned.32x32b.x32.b32 [%0], " \
        "{%1, %2, %3, %4, %5, %6, %7, %8, %9, %10, %11, %12, %13, %14, %15, %16, " \
        "%17, %18, %19, %20, %21, %22, %23, %24, %25, %26, %27, %28, %29, %30, %31, %32};" \
        :: "r"(tmem_addr), \
           "r"((r)[0]),"r"((r)[1]),"r"((r)[2]),"r"((r)[3]),"r"((r)[4]),"r"((r)[5]),"r"((r)[6]),"r"((r)[7]), \
           "r"((r)[8]),"r"((r)[9]),"r"((r)[10]),"r"((r)[11]),"r"((r)[12]),"r"((r)[13]),"r"((r)[14]),"r"((r)[15]), \
           "r"((r)[16]),"r"((r)[17]),"r"((r)[18]),"r"((r)[19]),"r"((r)[20]),"r"((r)[21]),"r"((r)[22]),"r"((r)[23]), \
           "r"((r)[24]),"r"((r)[25]),"r"((r)[26]),"r"((r)[27]),"r"((r)[28]),"r"((r)[29]),"r"((r)[30]),"r"((r)[31]) \
        : "memory")

#define TCGEN05_LD_X32(r, tmem_addr) \
    asm volatile("tcgen05.ld.sync.aligned.32x32b.x32.b32 " \
        "{%0, %1, %2, %3, %4, %5, %6, %7, %8, %9, %10, %11, %12, %13, %14, %15, " \
        "%16, %17, %18, %19, %20, %21, %22, %23, %24, %25, %26, %27, %28, %29, %30, %31}, [%32];" \
        : "=r"((r)[0]),"=r"((r)[1]),"=r"((r)[2]),"=r"((r)[3]),"=r"((r)[4]),"=r"((r)[5]),"=r"((r)[6]),"=r"((r)[7]), \
          "=r"((r)[8]),"=r"((r)[9]),"=r"((r)[10]),"=r"((r)[11]),"=r"((r)[12]),"=r"((r)[13]),"=r"((r)[14]),"=r"((r)[15]), \
          "=r"((r)[16]),"=r"((r)[17]),"=r"((r)[18]),"=r"((r)[19]),"=r"((r)[20]),"=r"((r)[21]),"=r"((r)[22]),"=r"((r)[23]), \
          "=r"((r)[24]),"=r"((r)[25]),"=r"((r)[26]),"=r"((r)[27]),"=r"((r)[28]),"=r"((r)[29]),"=r"((r)[30]),"=r"((r)[31]) \
        : "r"(tmem_addr))

__device__ __forceinline__ void cp_async16(uint32_t dst, const void* src) {
    asm volatile("cp.async.cg.shared.global [%0], [%1], 16;" :: "r"(dst), "l"(src));
}
#define CP_COMMIT() asm volatile("cp.async.commit_group;" ::: "memory")
#define CP_WAIT0()  asm volatile("cp.async.wait_group 0;" ::: "memory")

// TS-mode bf16 MMA: A in TMEM, B via SMEM descriptor
__device__ __forceinline__ void mma_f16_ts(uint32_t d_tmem, uint32_t a_tmem,
                                           uint64_t b_desc, uint32_t idesc, bool acc) {
    uint32_t en = acc ? 1u : 0u;
    uint32_t z = 0u;
    asm volatile("{\n\t.reg .pred p;\n\tsetp.ne.u32 p, %5, 0;\n\t"
        "tcgen05.mma.cta_group::1.kind::f16 [%0], [%1], %2, %3, {%4, %4, %4, %4}, p;\n\t}"
        :: "r"(d_tmem), "r"(a_tmem), "l"(b_desc), "r"(idesc), "r"(z), "r"(en)
        : "memory");
}

// SW128 K-major SMEM descriptor (LBO=1, SBO=64)
__device__ __forceinline__ uint64_t make_desc(uint32_t addr) {
    return (uint64_t(2) << 61) | (uint64_t(1) << 46) | (uint64_t(64) << 32)
         | (uint64_t(1) << 16) | ((addr >> 4) & 0x3FFF);
}

// idesc: F32 accum, bf16 A/B, M=128 (8<<24), N=64 (8<<17)
#define MMA_IDESC ((8u << 24) | (8u << 17) | (1u << 10) | (1u << 7) | (1u << 4))
#endif  // HAS_TCGEN05

__device__ __forceinline__ uint32_t smem_u32(const void* p) {
    uint32_t a;
    asm("{ .reg .u64 t; cvta.to.shared.u64 t, %1; cvt.u32.u64 %0, t; }" : "=r"(a) : "l"(p));
    return a;
}

// ============================================================
// Kernel 0: fused fp32->bf16x2 convert + per-row squared norm.
// One block per row, 128 threads.
// ============================================================
__global__ __launch_bounds__(128) void cvtsq_kernel(const float* __restrict__ X) {
    int row = blockIdx.x;
    int t = threadIdx.x;
    float4 v = *(const float4*)(X + (size_t)row * DIM + t * 4);
    uint32_t lo, hi;
    asm("cvt.rn.bf16x2.f32 %0, %1, %2;" : "=r"(lo) : "f"(v.y), "f"(v.x));
    asm("cvt.rn.bf16x2.f32 %0, %1, %2;" : "=r"(hi) : "f"(v.w), "f"(v.z));
    *(uint2*)(g_xb + (size_t)row * 256 + t * 2) = make_uint2(lo, hi);
    float s = v.x * v.x + v.y * v.y + v.z * v.z + v.w * v.w;
#pragma unroll
    for (int o = 16; o > 0; o >>= 1) s += __shfl_down_sync(0xffffffffu, s, o);
    __shared__ float ws[4];
    if ((t & 31) == 0) ws[t >> 5] = s;
    __syncthreads();
    if (t == 0) g_sq[row] = ws[0] + ws[1] + ws[2] + ws[3];
}

// ============================================================
// Kernel 1: pipelined tcgen05 bf16 GEMM + streaming top-3.
// 128 CTAs x 160 threads: warp0 = MMA issuer, warps1-4 = 128 row
// workers. A (128x512) resident in TMEM; B streamed as 64-col
// tiles (2x64KB double buffer, cp.async.cg); D double-buffered
// in TMEM (64+64 cols). Epilogue(t-1) overlaps MMA(t) and the
// cp.async transfer for tile t+1.
// key = sq[j] - 2*dot(i,j); ascending cols + strict < == jax ties.
// ============================================================
__global__ __launch_bounds__(160, 1)
void mma_topk_kernel() {
    extern __shared__ char smem[];
    const uint32_t smem_base = smem_u32(smem);
    const int tid = threadIdx.x;
    const int rowBase = blockIdx.x * 128;

#if HAS_TCGEN05
    const int wid = tid >> 5;
    const bool is_mma = (wid == 0);
    const int smsp = wid & 3;                    // worker subpartition
    const int row = smsp * 32 + (tid & 31);      // worker's TMEM lane / local row

    // ---- TMEM alloc + mbar init ----
    if (is_mma) {
        TCGEN05_ALLOC(smem_base + SMEM_TPTR, 512);
        TCGEN05_RELINQ();
    }
    if (tid == 0) {
        MBARRIER_INIT(smem_base + SMEM_MBAR0, 1);
        MBARRIER_INIT(smem_base + SMEM_MBAR1, 1);
    }
    __syncthreads();
    uint32_t tmem_base;
    asm volatile("ld.shared.b32 %0, [%1];" : "=r"(tmem_base) : "r"(smem_base + SMEM_TPTR));

    // ---- workers: store A (128 rows x 512 bf16) to TMEM ----
    if (!is_mma) {
        const uint4* arow = (const uint4*)g_xb + (size_t)(rowBase + row) * (DIM / 8);
        uint32_t wo = (uint32_t)smsp << 21;
#pragma unroll
        for (int c8 = 0; c8 < 8; ++c8) {
            uint32_t r[32];
#pragma unroll
            for (int u = 0; u < 8; ++u) {
                uint4 v = arow[c8 * 8 + u];
                r[u * 4 + 0] = v.x; r[u * 4 + 1] = v.y;
                r[u * 4 + 2] = v.z; r[u * 4 + 3] = v.w;
            }
            TCGEN05_ST_X32(tmem_base + TMEM_A + c8 * 32 + wo, r);
        }
        TCGEN05_WAIT_ST();
        TCGEN05_FENCE_BEFORE();
    }

    // ---- prologue: cp.async B tile 0 into buf0 + sq tile 0 slot 0 ----
    if (!is_mma) {
        const int wt = tid - 32;
#pragma unroll 4
        for (int l = 0; l < 32; ++l) {
            int f = wt + l * 128;
            int s = f >> 9, w = f & 511, j = w >> 3, u = w & 7;
            uint32_t bo = (uint32_t)(j * 128 + u * 16);
            uint32_t sw = bo ^ ((bo >> 3) & 0x70);
            cp_async16(smem_base + SMEM_B + s * 8192 + sw,
                       (const char*)g_xb + ((size_t)j * 256 + s * 32 + u * 4) * 4);
        }
    } else if ((tid & 31) < 16) {
        cp_async16(smem_base + SMEM_SQS + (tid & 15) * 16,
                   (const char*)g_sq + (tid & 15) * 16);
    }
    CP_COMMIT();
    CP_WAIT0();
    FENCE_PROXY_ASYNC();
    __syncthreads();

    // per-worker top-3 state
    float v0 = FLT_MAX, v1 = FLT_MAX, v2 = FLT_MAX;
    int   i0 = 0, i1 = 0, i2 = 0;

    for (int t = 0; t < NTILE; ++t) {
        if (is_mma) {
            // issue MMA(t) on buf[t&1] -> D[t&1], commit -> mbar[t&1]
            TCGEN05_FENCE_AFTER();
            if (elect_one()) {
                uint64_t bdesc = make_desc(smem_base + SMEM_B + (t & 1) * 65536);
                uint32_t dtm = tmem_base + ((t & 1) ? TMEM_D1 : TMEM_D0);
#pragma unroll
                for (int c = 0; c < 32; ++c) {
                    uint64_t bd = bdesc + (uint64_t)((c >> 2) * 512 + (c & 3) * 2);
                    mma_f16_ts(dtm, tmem_base + TMEM_A + c * 8, bd, MMA_IDESC, c > 0);
                }
                TCGEN05_COMMIT(smem_base + ((t & 1) ? SMEM_MBAR1 : SMEM_MBAR0));
            }
            // prefetch sq tile t+1 into slot (t+1)&3
            if (t + 1 < NTILE && (tid & 31) < 16) {
                cp_async16(smem_base + SMEM_SQS + ((t + 1) & 3) * 256 + (tid & 15) * 16,
                           (const char*)g_sq + (size_t)(t + 1) * 256 + (tid & 15) * 16);
            }
            CP_COMMIT();
            CP_WAIT0();
        } else {
            if (t >= 1) {
                // wait MMA(t-1) done
                uint32_t mb = smem_base + (((t - 1) & 1) ? SMEM_MBAR1 : SMEM_MBAR0);
                MBARRIER_WAIT_PARITY(mb, ((t - 1) >> 1) & 1);
                TCGEN05_FENCE_AFTER();
            }
            // issue cp.async for B tile t+1 into buf[(t+1)&1]
            // (safe: MMA(t-1), the last reader of that buffer, just completed)
            if (t + 1 < NTILE) {
                const int wt = tid - 32;
                const uint32_t bufo = SMEM_B + ((t + 1) & 1) * 65536;
                const size_t colw = (size_t)(t + 1) * 64 * 256;
#pragma unroll 4
                for (int l = 0; l < 32; ++l) {
                    int f = wt + l * 128;
                    int s = f >> 9, w = f & 511, j = w >> 3, u = w & 7;
                    uint32_t bo = (uint32_t)(j * 128 + u * 16);
                    uint32_t sw = bo ^ ((bo >> 3) & 0x70);
                    cp_async16(smem_base + bufo + s * 8192 + sw,
                               (const char*)g_xb + (colw + (size_t)j * 256 + s * 32 + u * 4) * 4);
                }
            }
            CP_COMMIT();

            if (t >= 1) {
                // epilogue(t-1): D[(t-1)&1], sq slot (t-1)&3
                const float* sqt = (const float*)(smem + SMEM_SQS + ((t - 1) & 3) * 256);
                const int colBase = (t - 1) * 64;
                const uint32_t dtm = tmem_base + (((t - 1) & 1) ? TMEM_D1 : TMEM_D0);
#pragma unroll
                for (int ch = 0; ch < 2; ++ch) {
                    uint32_t dr[32];
                    TCGEN05_LD_X32(dr, dtm + ch * 32);
                    TCGEN05_WAIT_LD();
#pragma unroll
                    for (int c = 0; c < 32; ++c) {
                        float key = fmaf(-2.f, __uint_as_float(dr[c]), sqt[ch * 32 + c]);
                        int col = colBase + ch * 32 + c;
                        if (key < v2) {
                            if (key < v1) {
                                v2 = v1; i2 = i1;
                                if (key < v0) { v1 = v0; i1 = i0; v0 = key; i0 = col; }
                                else          { v1 = key; i1 = col; }
                            } else { v2 = key; i2 = col; }
                        }
                    }
                }
                TCGEN05_FENCE_BEFORE();
            }
            CP_WAIT0();          // B tile t+1 landed
            FENCE_PROXY_ASYNC();
        }
        __syncthreads();
    }

    // ---- final epilogue: tile NTILE-1 ----
    if (!is_mma) {
        uint32_t mb = smem_base + (((NTILE - 1) & 1) ? SMEM_MBAR1 : SMEM_MBAR0);
        MBARRIER_WAIT_PARITY(mb, ((NTILE - 1) >> 1) & 1);
        TCGEN05_FENCE_AFTER();
        const float* sqt = (const float*)(smem + SMEM_SQS + ((NTILE - 1) & 3) * 256);
        const int colBase = (NTILE - 1) * 64;
        const uint32_t dtm = tmem_base + (((NTILE - 1) & 1) ? TMEM_D1 : TMEM_D0);
#pragma unroll
        for (int ch = 0; ch < 2; ++ch) {
            uint32_t dr[32];
            TCGEN05_LD_X32(dr, dtm + ch * 32);
            TCGEN05_WAIT_LD();
#pragma unroll
            for (int c = 0; c < 32; ++c) {
                float key = fmaf(-2.f, __uint_as_float(dr[c]), sqt[ch * 32 + c]);
                int col = colBase + ch * 32 + c;
                if (key < v2) {
                    if (key < v1) {
                        v2 = v1; i2 = i1;
                        if (key < v0) { v1 = v0; i1 = i0; v0 = key; i0 = col; }
                        else          { v1 = key; i1 = col; }
                    } else { v2 = key; i2 = col; }
                }
            }
        }
        TCGEN05_FENCE_BEFORE();
        g_neg[rowBase + row] = i2;
    }

    __syncthreads();
    if (is_mma) TCGEN05_DEALLOC(tmem_base, 512);

#else  // ---------------- SIMT fallback (non-'a' pass) ----------------
    float* As = (float*)(smem);               // [16][64]
    float* Bs = (float*)(smem + 4096);        // [16][128]
    float* mv = (float*)(smem + 12288);       // [64][48]
    int*   mi = (int*)(smem + 36864);         // [64][48]
    const int tx = tid & 15, ty = tid >> 4;
    const bool act = (tid < 128);

    for (int half = 0; half < 2; ++half) {
        const int rh = rowBase + half * 64;
        float tv[8][3]; int tii[8][3];
#pragma unroll
        for (int i = 0; i < 8; ++i)
#pragma unroll
            for (int q = 0; q < 3; ++q) { tv[i][q] = FLT_MAX; tii[i][q] = 0x7fffffff; }

        for (int jt = 0; jt < NROW / 128; ++jt) {
            const int colBase = jt * 128;
            float c[8][8];
#pragma unroll
            for (int i = 0; i < 8; ++i)
#pragma unroll
                for (int j = 0; j < 8; ++j) c[i][j] = 0.f;

            for (int kt = 0; kt < DIM; kt += 16) {
                __syncthreads();
                if (act) {
#pragma unroll
                    for (int l = 0; l < 4; ++l) {
                        int f = tid + l * 128;
                        int r = f >> 3, u = f & 7;
                        uint32_t w = g_xb[(size_t)(rh + r) * 256 + kt / 2 + u];
                        __nv_bfloat162 b2 = *(__nv_bfloat162*)&w;
                        float2 f2 = __bfloat1622float2(b2);
                        As[(2 * u + 0) * 64 + r] = f2.x;
                        As[(2 * u + 1) * 64 + r] = f2.y;
                    }
#pragma unroll
                    for (int l = 0; l < 8; ++l) {
                        int f = tid + l * 128;
                        int r = f >> 3, u = f & 7;
                        uint32_t w = g_xb[(size_t)(colBase + r) * 256 + kt / 2 + u];
                        __nv_bfloat162 b2 = *(__nv_bfloat162*)&w;
                        float2 f2 = __bfloat1622float2(b2);
                        Bs[(2 * u + 0) * 128 + r] = f2.x;
                        Bs[(2 * u + 1) * 128 + r] = f2.y;
                    }
                }
                __syncthreads();
                if (act) {
#pragma unroll
                    for (int kk = 0; kk < 16; ++kk) {
                        float a[8], b[8];
#pragma unroll
                        for (int i = 0; i < 8; ++i) a[i] = As[kk * 64 + ty * 8 + i];
#pragma unroll
                        for (int j = 0; j < 8; ++j) b[j] = Bs[kk * 128 + tx * 8 + j];
#pragma unroll
                        for (int i = 0; i < 8; ++i)
#pragma unroll
                            for (int j = 0; j < 8; ++j) c[i][j] += a[i] * b[j];
                    }
                }
            }
            if (act) {
#pragma unroll
                for (int j = 0; j < 8; ++j) {
                    int col = colBase + tx * 8 + j;
                    float sqc = g_sq[col];
#pragma unroll
                    for (int i = 0; i < 8; ++i) {
                        float d2 = fmaf(-2.f, c[i][j], sqc);
                        bool b2c = (d2 < tv[i][2]) || (d2 == tv[i][2] && col < tii[i][2]);
                        if (b2c) {
                            bool b1c = (d2 < tv[i][1]) || (d2 == tv[i][1] && col < tii[i][1]);
                            bool b0c = (d2 < tv[i][0]) || (d2 == tv[i][0] && col < tii[i][0]);
                            if (b0c) {
                                tv[i][2] = tv[i][1]; tii[i][2] = tii[i][1];
                                tv[i][1] = tv[i][0]; tii[i][1] = tii[i][0];
                                tv[i][0] = d2;       tii[i][0] = col;
                            } else if (b1c) {
                                tv[i][2] = tv[i][1]; tii[i][2] = tii[i][1];
                                tv[i][1] = d2;       tii[i][1] = col;
                            } else { tv[i][2] = d2; tii[i][2] = col; }
                        }
                    }
                }
            }
        }

        __syncthreads();
        if (act) {
#pragma unroll
            for (int i = 0; i < 8; ++i)
#pragma unroll
                for (int q = 0; q < 3; ++q) {
                    mv[(ty * 8 + i) * 48 + tx * 3 + q] = tv[i][q];
                    mi[(ty * 8 + i) * 48 + tx * 3 + q] = tii[i][q];
                }
        }
        __syncthreads();
        if (tid < 64) {
            float w0 = FLT_MAX, w1 = FLT_MAX, w2 = FLT_MAX;
            int   j0 = 0x7fffffff, j1 = 0x7fffffff, j2 = 0x7fffffff;
            for (int cnd = 0; cnd < 48; ++cnd) {
                float d = mv[tid * 48 + cnd];
                int   ix = mi[tid * 48 + cnd];
                bool b2c = (d < w2) || (d == w2 && ix < j2);
                if (b2c) {
                    bool b1c = (d < w1) || (d == w1 && ix < j1);
                    bool b0c = (d < w0) || (d == w0 && ix < j0);
                    if (b0c)      { w2 = w1; j2 = j1; w1 = w0; j1 = j0; w0 = d; j0 = ix; }
                    else if (b1c) { w2 = w1; j2 = j1; w1 = d; j1 = ix; }
                    else          { w2 = d;  j2 = ix; }
                }
            }
            g_neg[rh + tid] = j2;
        }
        __syncthreads();
    }
#endif
}

// ============================================================
// Kernel 2: per-row triplet loss (one warp per row, fp32 exact)
// ============================================================
__global__ __launch_bounds__(256) void rowloss_kernel(const float* __restrict__ X,
                                                      const float* __restrict__ P) {
    int warp = threadIdx.x >> 5;
    int lane = threadIdx.x & 31;
    int row = blockIdx.x * 8 + warp;
    const float4* xr = (const float4*)(X + (size_t)row * DIM);
    const float4* pr = (const float4*)(P + (size_t)row * DIM);
    const float4* nr = (const float4*)(X + (size_t)g_neg[row] * DIM);
    float sap = 0.f, san = 0.f;
#pragma unroll
    for (int i = 0; i < 4; ++i) {
        float4 x = xr[lane + 32 * i];
        float4 p = pr[lane + 32 * i];
        float4 v = nr[lane + 32 * i];
        float d;
        d = x.x - p.x + EPSV; sap += d * d;
        d = x.y - p.y + EPSV; sap += d * d;
        d = x.z - p.z + EPSV; sap += d * d;
        d = x.w - p.w + EPSV; sap += d * d;
        d = x.x - v.x + EPSV; san += d * d;
        d = x.y - v.y + EPSV; san += d * d;
        d = x.z - v.z + EPSV; san += d * d;
        d = x.w - v.w + EPSV; san += d * d;
    }
#pragma unroll
    for (int o = 16; o > 0; o >>= 1) {
        sap += __shfl_down_sync(0xffffffffu, sap, o);
        san += __shfl_down_sync(0xffffffffu, san, o);
    }
    if (lane == 0)
        g_rowloss[row] = fmaxf(sqrtf(sap) - sqrtf(san) + MARGIN, 0.f);
}

// ============================================================
// Kernel 3: mean reduction -> d_out[0]
// ============================================================
__global__ __launch_bounds__(512) void reduce_kernel(float* __restrict__ out) {
    int t = threadIdx.x;
    float s = 0.f;
    for (int i = t; i < NROW; i += 512) s += g_rowloss[i];
#pragma unroll
    for (int o = 16; o > 0; o >>= 1) s += __shfl_down_sync(0xffffffffu, s, o);
    __shared__ float ws[16];
    if ((t & 31) == 0) ws[t >> 5] = s;
    __syncthreads();
    if (t == 0) {
        float tot = 0.f;
#pragma unroll
        for (int w = 0; w < 16; ++w) tot += ws[w];
        out[0] = tot / (float)NROW;
    }
}

extern "C" void kernel_launch(void* const* d_in, const int* in_sizes, int n_in,
                              void* d_out, int out_size) {
    const float* X = (const float*)d_in[0];   // inputs  [16384, 512] f32
    const float* P = (const float*)d_in[1];   // positive[16384, 512] f32
    float* out = (float*)d_out;

    cudaFuncSetAttribute(mma_topk_kernel,
                         cudaFuncAttributeMaxDynamicSharedMemorySize, SMEM_TOTAL);

    cvtsq_kernel<<<NROW, 128>>>(X);
    mma_topk_kernel<<<128, 160, SMEM_TOTAL>>>();
    rowloss_kernel<<<NROW / 8, 256>>>(X, P);
    reduce_kernel<<<1, 512>>>(out);
}

// round 5
// speedup vs baseline: 16.7197x; 1.0218x over previous
#include <cuda_runtime.h>
#include <cuda_bf16.h>
#include <math.h>
#include <float.h>
#include <stdint.h>

#define NROW 16384
#define DIM  512
#define MARGIN 2.0f
#define EPSV 1e-6f

// Arch-specific (sm_103a) feature gate: tcgen05/TMEM PTX only exists in the
// 'a' compilation pass. The plain compute_103/sm_103 pass gets a SIMT fallback.
#if defined(__CUDA_ARCH_FEAT_SM103_ALL) || (defined(__CUDA_ARCH_SPECIFIC__) && (__CUDA_ARCH_SPECIFIC__ == 1030))
#define HAS_TCGEN05 1
#else
#define HAS_TCGEN05 0
#endif

// ---- device scratch (no dynamic allocation allowed) ----
__device__ float g_sq[NROW];
__device__ int   g_neg[NROW];
__device__ float g_rowloss[NROW];
__device__ __align__(16) uint32_t g_xb[NROW * DIM / 2];   // bf16x2-packed inputs

// SMEM layout (dynamic), tcgen05 path
#define SMEM_TPTR  0
#define SMEM_MBAR0 8
#define SMEM_MBAR1 16
#define SMEM_SQS   32            // 4 slots x 256B
#define SMEM_B     2048          // 3 x 65536 (N=64 tile: 64 rows x 512 K bf16)
#define SMEM_TOTAL (2048 + 3 * 65536)

#define TMEM_A  0                // 256 cols: A 128x512 bf16
#define TMEM_D0 256              // 64 cols: D 128x64 f32
#define TMEM_D1 320

#define NTILE 256                // 16384 / 64 column tiles

#if HAS_TCGEN05
// ============================================================
// PTX helpers (sm_103a tcgen05 / mbarrier / cp.async)
// ============================================================
__device__ __forceinline__ uint32_t elect_one() {
    uint32_t p;
    asm volatile("{\n\t.reg .pred p;\n\telect.sync _|p, 0xFFFFFFFF;\n\tselp.b32 %0, 1, 0, p;\n\t}" : "=r"(p));
    return p;
}
#define TCGEN05_ALLOC(dst, n) \
    asm volatile("tcgen05.alloc.cta_group::1.sync.aligned.shared::cta.b32 [%0], %1;" :: "r"(dst), "r"(n) : "memory")
#define TCGEN05_DEALLOC(t, n) \
    asm volatile("tcgen05.dealloc.cta_group::1.sync.aligned.b32 %0, %1;" :: "r"(t), "r"(n))
#define TCGEN05_RELINQ() \
    asm volatile("tcgen05.relinquish_alloc_permit.cta_group::1.sync.aligned;")
#define TCGEN05_WAIT_ST() asm volatile("tcgen05.wait::st.sync.aligned;" ::: "memory")
#define TCGEN05_WAIT_LD() asm volatile("tcgen05.wait::ld.sync.aligned;" ::: "memory")
#define TCGEN05_FENCE_BEFORE() asm volatile("tcgen05.fence::before_thread_sync;" ::: "memory")
#define TCGEN05_FENCE_AFTER()  asm volatile("tcgen05.fence::after_thread_sync;" ::: "memory")
#define FENCE_PROXY_ASYNC() asm volatile("fence.proxy.async.shared::cta;" ::: "memory")
#define MBARRIER_INIT(m, c) \
    asm volatile("mbarrier.init.shared.b64 [%0], %1;" :: "r"(m), "r"(c) : "memory")
#define TCGEN05_COMMIT(m) \
    asm volatile("tcgen05.commit.cta_group::1.mbarrier::arrive::one.shared::cluster.b64 [%0];" :: "r"(m) : "memory")

#define MBARRIER_WAIT_PARITY(mbar_smem_addr, phase_parity) do { \
    uint32_t _mbar = (uint32_t)(mbar_smem_addr); \
    uint32_t _parity = (uint32_t)(phase_parity); \
    uint32_t _done; \
    asm volatile("{\n\t.reg .pred p;\n\t" \
        "mbarrier.try_wait.parity.acquire.cta.shared::cta.b64 p, [%1], %2;\n\t" \
        "selp.b32 %0, 1, 0, p;\n\t}" : "=r"(_done) : "r"(_mbar), "r"(_parity) : "memory"); \
    if (!_done) { \
        asm volatile("{\n\t.reg .pred P1;\n\t" \
            "WAIT_LOOP_%=:\n\t" \
            "mbarrier.try_wait.parity.acquire.cta.shared::cta.b64 P1, [%0], %1, 0x989680;\n\t" \
            "@P1 bra.uni WAIT_DONE_%=;\n\t" \
            "bra.uni WAIT_LOOP_%=;\n\t" \
            "WAIT_DONE_%=:\n\t}" :: "r"(_mbar), "r"(_parity) : "memory"); \
    } \
} while (0)

#define TCGEN05_ST_X32(tmem_addr, r) \
    asm volatile("tcgen05.st.sync.aligned.32x32b.x32.b32 [%0], " \
        "{%1, %2, %3, %4, %5, %6, %7, %8, %9, %10, %11, %12, %13, %14, %15, %16, " \
        "%17, %18, %19, %20, %21, %22, %23, %24, %25, %26, %27, %28, %29, %30, %31, %32};" \
        :: "r"(tmem_addr), \
           "r"((r)[0]),"r"((r)[1]),"r"((r)[2]),"r"((r)[3]),"r"((r)[4]),"r"((r)[5]),"r"((r)[6]),"r"((r)[7]), \
           "r"((r)[8]),"r"((r)[9]),"r"((r)[10]),"r"((r)[11]),"r"((r)[12]),"r"((r)[13]),"r"((r)[14]),"r"((r)[15]), \
           "r"((r)[16]),"r"((r)[17]),"r"((r)[18]),"r"((r)[19]),"r"((r)[20]),"r"((r)[21]),"r"((r)[22]),"r"((r)[23]), \
           "r"((r)[24]),"r"((r)[25]),"r"((r)[26]),"r"((r)[27]),"r"((r)[28]),"r"((r)[29]),"r"((r)[30]),"r"((r)[31]) \
        : "memory")

#define TCGEN05_LD_X32(r, tmem_addr) \
    asm volatile("tcgen05.ld.sync.aligned.32x32b.x32.b32 " \
        "{%0, %1, %2, %3, %4, %5, %6, %7, %8, %9, %10, %11, %12, %13, %14, %15, " \
        "%16, %17, %18, %19, %20, %21, %22, %23, %24, %25, %26, %27, %28, %29, %30, %31}, [%32];" \
        : "=r"((r)[0]),"=r"((r)[1]),"=r"((r)[2]),"=r"((r)[3]),"=r"((r)[4]),"=r"((r)[5]),"=r"((r)[6]),"=r"((r)[7]), \
          "=r"((r)[8]),"=r"((r)[9]),"=r"((r)[10]),"=r"((r)[11]),"=r"((r)[12]),"=r"((r)[13]),"=r"((r)[14]),"=r"((r)[15]), \
          "=r"((r)[16]),"=r"((r)[17]),"=r"((r)[18]),"=r"((r)[19]),"=r"((r)[20]),"=r"((r)[21]),"=r"((r)[22]),"=r"((r)[23]), \
          "=r"((r)[24]),"=r"((r)[25]),"=r"((r)[26]),"=r"((r)[27]),"=r"((r)[28]),"=r"((r)[29]),"=r"((r)[30]),"=r"((r)[31]) \
        : "r"(tmem_addr))

__device__ __forceinline__ void cp_async16(uint32_t dst, const void* src) {
    asm volatile("cp.async.cg.shared.global [%0], [%1], 16;" :: "r"(dst), "l"(src));
}
#define CP_COMMIT() asm volatile("cp.async.commit_group;" ::: "memory")
#define CP_WAIT0()  asm volatile("cp.async.wait_group 0;" ::: "memory")
#define CP_WAIT1()  asm volatile("cp.async.wait_group 1;" ::: "memory")

// TS-mode bf16 MMA: A in TMEM, B via SMEM descriptor
__device__ __forceinline__ void mma_f16_ts(uint32_t d_tmem, uint32_t a_tmem,
                                           uint64_t b_desc, uint32_t idesc, bool acc) {
    uint32_t en = acc ? 1u : 0u;
    uint32_t z = 0u;
    asm volatile("{\n\t.reg .pred p;\n\tsetp.ne.u32 p, %5, 0;\n\t"
        "tcgen05.mma.cta_group::1.kind::f16 [%0], [%1], %2, %3, {%4, %4, %4, %4}, p;\n\t}"
        :: "r"(d_tmem), "r"(a_tmem), "l"(b_desc), "r"(idesc), "r"(z), "r"(en)
        : "memory");
}

// SW128 K-major SMEM descriptor (LBO=1, SBO=64)
__device__ __forceinline__ uint64_t make_desc(uint32_t addr) {
    return (uint64_t(2) << 61) | (uint64_t(1) << 46) | (uint64_t(64) << 32)
         | (uint64_t(1) << 16) | ((addr >> 4) & 0x3FFF);
}

// idesc: F32 accum, bf16 A/B, M=128 (8<<24), N=64 (8<<17)
#define MMA_IDESC ((8u << 24) | (8u << 17) | (1u << 10) | (1u << 7) | (1u << 4))
#endif  // HAS_TCGEN05

__device__ __forceinline__ uint32_t smem_u32(const void* p) {
    uint32_t a;
    asm("{ .reg .u64 t; cvta.to.shared.u64 t, %1; cvt.u32.u64 %0, t; }" : "=r"(a) : "l"(p));
    return a;
}

// ============================================================
// Kernel 0: fused fp32->bf16x2 convert + per-row squared norm.
// ============================================================
__global__ __launch_bounds__(128) void cvtsq_kernel(const float* __restrict__ X) {
    int row = blockIdx.x;
    int t = threadIdx.x;
    float4 v = *(const float4*)(X + (size_t)row * DIM + t * 4);
    uint32_t lo, hi;
    asm("cvt.rn.bf16x2.f32 %0, %1, %2;" : "=r"(lo) : "f"(v.y), "f"(v.x));
    asm("cvt.rn.bf16x2.f32 %0, %1, %2;" : "=r"(hi) : "f"(v.w), "f"(v.z));
    *(uint2*)(g_xb + (size_t)row * 256 + t * 2) = make_uint2(lo, hi);
    float s = v.x * v.x + v.y * v.y + v.z * v.z + v.w * v.w;
#pragma unroll
    for (int o = 16; o > 0; o >>= 1) s += __shfl_down_sync(0xffffffffu, s, o);
    __shared__ float ws[4];
    if ((t & 31) == 0) ws[t >> 5] = s;
    __syncthreads();
    if (t == 0) g_sq[row] = ws[0] + ws[1] + ws[2] + ws[3];
}

// ============================================================
// Kernel 1: 3-stage pipelined tcgen05 bf16 GEMM + streaming top-3.
// 128 CTAs x 160 threads: warp0 = MMA issuer, warps1-4 = 128 row
// workers. A (128x512) resident in TMEM; B streamed as 64-col
// tiles through a 3-deep cp.async ring; D double-buffered in TMEM.
// At iter t: MMA(t), epilogue(t-1), issue load(t+2), wait load(t+1).
// key = sq[j] - 2*dot(i,j); ascending cols + strict < == jax ties.
// ============================================================
__global__ __launch_bounds__(160, 1)
void mma_topk_kernel() {
    extern __shared__ char smem[];
    const uint32_t smem_base = smem_u32(smem);
    const int tid = threadIdx.x;
    const int rowBase = blockIdx.x * 128;

#if HAS_TCGEN05
    const int wid = tid >> 5;
    const bool is_mma = (wid == 0);
    const int smsp = wid & 3;                    // worker subpartition
    const int row = smsp * 32 + (tid & 31);      // worker's TMEM lane / local row

    // ---- TMEM alloc + mbar init ----
    if (is_mma) {
        TCGEN05_ALLOC(smem_base + SMEM_TPTR, 512);
        TCGEN05_RELINQ();
    }
    if (tid == 0) {
        MBARRIER_INIT(smem_base + SMEM_MBAR0, 1);
        MBARRIER_INIT(smem_base + SMEM_MBAR1, 1);
    }
    __syncthreads();
    uint32_t tmem_base;
    asm volatile("ld.shared.b32 %0, [%1];" : "=r"(tmem_base) : "r"(smem_base + SMEM_TPTR));

    // ---- workers: store A (128 rows x 512 bf16) to TMEM ----
    if (!is_mma) {
        const uint4* arow = (const uint4*)g_xb + (size_t)(rowBase + row) * (DIM / 8);
        uint32_t wo = (uint32_t)smsp << 21;
#pragma unroll
        for (int c8 = 0; c8 < 8; ++c8) {
            uint32_t r[32];
#pragma unroll
            for (int u = 0; u < 8; ++u) {
                uint4 v = arow[c8 * 8 + u];
                r[u * 4 + 0] = v.x; r[u * 4 + 1] = v.y;
                r[u * 4 + 2] = v.z; r[u * 4 + 3] = v.w;
            }
            TCGEN05_ST_X32(tmem_base + TMEM_A + c8 * 32 + wo, r);
        }
        TCGEN05_WAIT_ST();
        TCGEN05_FENCE_BEFORE();
    }

    // ---- prologue: cp.async B tiles 0,1 (two groups) + sq tiles 0,1 ----
    if (!is_mma) {
        const int wt = tid - 32;
#pragma unroll
        for (int pt = 0; pt < 2; ++pt) {
            const uint32_t bufo = SMEM_B + pt * 65536;
            const size_t colw = (size_t)pt * 64 * 256;
#pragma unroll 4
            for (int l = 0; l < 32; ++l) {
                int f = wt + l * 128;
                int s = f >> 9, w = f & 511, j = w >> 3, u = w & 7;
                uint32_t bo = (uint32_t)(j * 128 + u * 16);
                uint32_t sw = bo ^ ((bo >> 3) & 0x70);
                cp_async16(smem_base + bufo + s * 8192 + sw,
                           (const char*)g_xb + (colw + (size_t)j * 256 + s * 32 + u * 4) * 4);
            }
            CP_COMMIT();
        }
        CP_WAIT1();          // tile 0 landed; tile 1 may be in flight
    } else {
        if ((tid & 31) < 16) {
            cp_async16(smem_base + SMEM_SQS + (tid & 15) * 16,
                       (const char*)g_sq + (tid & 15) * 16);
            cp_async16(smem_base + SMEM_SQS + 256 + (tid & 15) * 16,
                       (const char*)g_sq + 256 + (tid & 15) * 16);
        }
        CP_COMMIT();
        CP_WAIT0();
    }
    FENCE_PROXY_ASYNC();
    __syncthreads();

    // per-worker top-3 state
    float v0 = FLT_MAX, v1 = FLT_MAX, v2 = FLT_MAX;
    int   i0 = 0, i1 = 0, i2 = 0;

    // buffer index cycling: buf(t) = t % 3
    int b_cur = 0;                 // t % 3
    int b_nxt2 = 2;                // (t+2) % 3

    for (int t = 0; t < NTILE; ++t) {
        if (is_mma) {
            // issue MMA(t) on buf[t%3] -> D[t&1], commit -> mbar[t&1]
            TCGEN05_FENCE_AFTER();
            if (elect_one()) {
                uint64_t bdesc = make_desc(smem_base + SMEM_B + b_cur * 65536);
                uint32_t dtm = tmem_base + ((t & 1) ? TMEM_D1 : TMEM_D0);
#pragma unroll
                for (int c = 0; c < 32; ++c) {
                    uint64_t bd = bdesc + (uint64_t)((c >> 2) * 512 + (c & 3) * 2);
                    mma_f16_ts(dtm, tmem_base + TMEM_A + c * 8, bd, MMA_IDESC, c > 0);
                }
                TCGEN05_COMMIT(smem_base + ((t & 1) ? SMEM_MBAR1 : SMEM_MBAR0));
            }
            // prefetch sq tile t+2 into slot (t+2)&3
            if (t + 2 < NTILE && (tid & 31) < 16) {
                cp_async16(smem_base + SMEM_SQS + ((t + 2) & 3) * 256 + (tid & 15) * 16,
                           (const char*)g_sq + (size_t)(t + 2) * 256 + (tid & 15) * 16);
            }
            CP_COMMIT();
            CP_WAIT0();
        } else {
            if (t >= 1) {
                // wait MMA(t-1) done (frees buf[(t-1)%3] == buf[(t+2)%3])
                uint32_t mb = smem_base + (((t - 1) & 1) ? SMEM_MBAR1 : SMEM_MBAR0);
                MBARRIER_WAIT_PARITY(mb, ((t - 1) >> 1) & 1);
                TCGEN05_FENCE_AFTER();
            }
            // issue cp.async for B tile t+2 into buf[(t+2)%3]
            if (t + 2 < NTILE) {
                const int wt = tid - 32;
                const uint32_t bufo = SMEM_B + b_nxt2 * 65536;
                const size_t colw = (size_t)(t + 2) * 64 * 256;
#pragma unroll 4
                for (int l = 0; l < 32; ++l) {
                    int f = wt + l * 128;
                    int s = f >> 9, w = f & 511, j = w >> 3, u = w & 7;
                    uint32_t bo = (uint32_t)(j * 128 + u * 16);
                    uint32_t sw = bo ^ ((bo >> 3) & 0x70);
                    cp_async16(smem_base + bufo + s * 8192 + sw,
                               (const char*)g_xb + (colw + (size_t)j * 256 + s * 32 + u * 4) * 4);
                }
            }
            CP_COMMIT();

            if (t >= 1) {
                // epilogue(t-1): D[(t-1)&1], sq slot (t-1)&3
                const float* sqt = (const float*)(smem + SMEM_SQS + ((t - 1) & 3) * 256);
                const int colBase = (t - 1) * 64;
                const uint32_t dtm = tmem_base + (((t - 1) & 1) ? TMEM_D1 : TMEM_D0);
                uint32_t dr[64];
                TCGEN05_LD_X32(dr, dtm);
                TCGEN05_LD_X32(dr + 32, dtm + 32);
                TCGEN05_WAIT_LD();
#pragma unroll
                for (int c = 0; c < 64; ++c) {
                    float key = fmaf(-2.f, __uint_as_float(dr[c]), sqt[c]);
                    int col = colBase + c;
                    if (key < v2) {
                        if (key < v1) {
                            v2 = v1; i2 = i1;
                            if (key < v0) { v1 = v0; i1 = i0; v0 = key; i0 = col; }
                            else          { v1 = key; i1 = col; }
                        } else { v2 = key; i2 = col; }
                    }
                }
                TCGEN05_FENCE_BEFORE();
            }
            CP_WAIT1();          // B tile t+1 landed (issued last iteration)
            FENCE_PROXY_ASYNC();
        }
        __syncthreads();
        b_cur = (b_cur == 2) ? 0 : b_cur + 1;
        b_nxt2 = (b_nxt2 == 2) ? 0 : b_nxt2 + 1;
    }

    // ---- final epilogue: tile NTILE-1 ----
    if (!is_mma) {
        uint32_t mb = smem_base + (((NTILE - 1) & 1) ? SMEM_MBAR1 : SMEM_MBAR0);
        MBARRIER_WAIT_PARITY(mb, ((NTILE - 1) >> 1) & 1);
        TCGEN05_FENCE_AFTER();
        const float* sqt = (const float*)(smem + SMEM_SQS + ((NTILE - 1) & 3) * 256);
        const int colBase = (NTILE - 1) * 64;
        const uint32_t dtm = tmem_base + (((NTILE - 1) & 1) ? TMEM_D1 : TMEM_D0);
        uint32_t dr[64];
        TCGEN05_LD_X32(dr, dtm);
        TCGEN05_LD_X32(dr + 32, dtm + 32);
        TCGEN05_WAIT_LD();
#pragma unroll
        for (int c = 0; c < 64; ++c) {
            float key = fmaf(-2.f, __uint_as_float(dr[c]), sqt[c]);
            int col = colBase + c;
            if (key < v2) {
                if (key < v1) {
                    v2 = v1; i2 = i1;
                    if (key < v0) { v1 = v0; i1 = i0; v0 = key; i0 = col; }
                    else          { v1 = key; i1 = col; }
                } else { v2 = key; i2 = col; }
            }
        }
        TCGEN05_FENCE_BEFORE();
        g_neg[rowBase + row] = i2;
    }

    __syncthreads();
    if (is_mma) TCGEN05_DEALLOC(tmem_base, 512);

#else  // ---------------- SIMT fallback (non-'a' pass) ----------------
    float* As = (float*)(smem);               // [16][64]
    float* Bs = (float*)(smem + 4096);        // [16][128]
    float* mv = (float*)(smem + 12288);       // [64][48]
    int*   mi = (int*)(smem + 36864);         // [64][48]
    const int tx = tid & 15, ty = tid >> 4;
    const bool act = (tid < 128);

    for (int half = 0; half < 2; ++half) {
        const int rh = rowBase + half * 64;
        float tv[8][3]; int tii[8][3];
#pragma unroll
        for (int i = 0; i < 8; ++i)
#pragma unroll
            for (int q = 0; q < 3; ++q) { tv[i][q] = FLT_MAX; tii[i][q] = 0x7fffffff; }

        for (int jt = 0; jt < NROW / 128; ++jt) {
            const int colBase = jt * 128;
            float c[8][8];
#pragma unroll
            for (int i = 0; i < 8; ++i)
#pragma unroll
                for (int j = 0; j < 8; ++j) c[i][j] = 0.f;

            for (int kt = 0; kt < DIM; kt += 16) {
                __syncthreads();
                if (act) {
#pragma unroll
                    for (int l = 0; l < 4; ++l) {
                        int f = tid + l * 128;
                        int r = f >> 3, u = f & 7;
                        uint32_t w = g_xb[(size_t)(rh + r) * 256 + kt / 2 + u];
                        __nv_bfloat162 b2 = *(__nv_bfloat162*)&w;
                        float2 f2 = __bfloat1622float2(b2);
                        As[(2 * u + 0) * 64 + r] = f2.x;
                        As[(2 * u + 1) * 64 + r] = f2.y;
                    }
#pragma unroll
                    for (int l = 0; l < 8; ++l) {
                        int f = tid + l * 128;
                        int r = f >> 3, u = f & 7;
                        uint32_t w = g_xb[(size_t)(colBase + r) * 256 + kt / 2 + u];
                        __nv_bfloat162 b2 = *(__nv_bfloat162*)&w;
                        float2 f2 = __bfloat1622float2(b2);
                        Bs[(2 * u + 0) * 128 + r] = f2.x;
                        Bs[(2 * u + 1) * 128 + r] = f2.y;
                    }
                }
                __syncthreads();
                if (act) {
#pragma unroll
                    for (int kk = 0; kk < 16; ++kk) {
                        float a[8], b[8];
#pragma unroll
                        for (int i = 0; i < 8; ++i) a[i] = As[kk * 64 + ty * 8 + i];
#pragma unroll
                        for (int j = 0; j < 8; ++j) b[j] = Bs[kk * 128 + tx * 8 + j];
#pragma unroll
                        for (int i = 0; i < 8; ++i)
#pragma unroll
                            for (int j = 0; j < 8; ++j) c[i][j] += a[i] * b[j];
                    }
                }
            }
            if (act) {
#pragma unroll
                for (int j = 0; j < 8; ++j) {
                    int col = colBase + tx * 8 + j;
                    float sqc = g_sq[col];
#pragma unroll
                    for (int i = 0; i < 8; ++i) {
                        float d2 = fmaf(-2.f, c[i][j], sqc);
                        bool b2c = (d2 < tv[i][2]) || (d2 == tv[i][2] && col < tii[i][2]);
                        if (b2c) {
                            bool b1c = (d2 < tv[i][1]) || (d2 == tv[i][1] && col < tii[i][1]);
                            bool b0c = (d2 < tv[i][0]) || (d2 == tv[i][0] && col < tii[i][0]);
                            if (b0c) {
                                tv[i][2] = tv[i][1]; tii[i][2] = tii[i][1];
                                tv[i][1] = tv[i][0]; tii[i][1] = tii[i][0];
                                tv[i][0] = d2;       tii[i][0] = col;
                            } else if (b1c) {
                                tv[i][2] = tv[i][1]; tii[i][2] = tii[i][1];
                                tv[i][1] = d2;       tii[i][1] = col;
                            } else { tv[i][2] = d2; tii[i][2] = col; }
                        }
                    }
                }
            }
        }

        __syncthreads();
        if (act) {
#pragma unroll
            for (int i = 0; i < 8; ++i)
#pragma unroll
                for (int q = 0; q < 3; ++q) {
                    mv[(ty * 8 + i) * 48 + tx * 3 + q] = tv[i][q];
                    mi[(ty * 8 + i) * 48 + tx * 3 + q] = tii[i][q];
                }
        }
        __syncthreads();
        if (tid < 64) {
            float w0 = FLT_MAX, w1 = FLT_MAX, w2 = FLT_MAX;
            int   j0 = 0x7fffffff, j1 = 0x7fffffff, j2 = 0x7fffffff;
            for (int cnd = 0; cnd < 48; ++cnd) {
                float d = mv[tid * 48 + cnd];
                int   ix = mi[tid * 48 + cnd];
                bool b2c = (d < w2) || (d == w2 && ix < j2);
                if (b2c) {
                    bool b1c = (d < w1) || (d == w1 && ix < j1);
                    bool b0c = (d < w0) || (d == w0 && ix < j0);
                    if (b0c)      { w2 = w1; j2 = j1; w1 = w0; j1 = j0; w0 = d; j0 = ix; }
                    else if (b1c) { w2 = w1; j2 = j1; w1 = d; j1 = ix; }
                    else          { w2 = d;  j2 = ix; }
                }
            }
            g_neg[rh + tid] = j2;
        }
        __syncthreads();
    }
#endif
}

// ============================================================
// Kernel 2: per-row triplet loss (one warp per row, fp32 exact)
// ============================================================
__global__ __launch_bounds__(256) void rowloss_kernel(const float* __restrict__ X,
                                                      const float* __restrict__ P) {
    int warp = threadIdx.x >> 5;
    int lane = threadIdx.x & 31;
    int row = blockIdx.x * 8 + warp;
    const float4* xr = (const float4*)(X + (size_t)row * DIM);
    const float4* pr = (const float4*)(P + (size_t)row * DIM);
    const float4* nr = (const float4*)(X + (size_t)g_neg[row] * DIM);
    float sap = 0.f, san = 0.f;
#pragma unroll
    for (int i = 0; i < 4; ++i) {
        float4 x = xr[lane + 32 * i];
        float4 p = pr[lane + 32 * i];
        float4 v = nr[lane + 32 * i];
        float d;
        d = x.x - p.x + EPSV; sap += d * d;
        d = x.y - p.y + EPSV; sap += d * d;
        d = x.z - p.z + EPSV; sap += d * d;
        d = x.w - p.w + EPSV; sap += d * d;
        d = x.x - v.x + EPSV; san += d * d;
        d = x.y - v.y + EPSV; san += d * d;
        d = x.z - v.z + EPSV; san += d * d;
        d = x.w - v.w + EPSV; san += d * d;
    }
#pragma unroll
    for (int o = 16; o > 0; o >>= 1) {
        sap += __shfl_down_sync(0xffffffffu, sap, o);
        san += __shfl_down_sync(0xffffffffu, san, o);
    }
    if (lane == 0)
        g_rowloss[row] = fmaxf(sqrtf(sap) - sqrtf(san) + MARGIN, 0.f);
}

// ============================================================
// Kernel 3: mean reduction -> d_out[0]
// ============================================================
__global__ __launch_bounds__(512) void reduce_kernel(float* __restrict__ out) {
    int t = threadIdx.x;
    float s = 0.f;
    for (int i = t; i < NROW; i += 512) s += g_rowloss[i];
#pragma unroll
    for (int o = 16; o > 0; o >>= 1) s += __shfl_down_sync(0xffffffffu, s, o);
    __shared__ float ws[16];
    if ((t & 31) == 0) ws[t >> 5] = s;
    __syncthreads();
    if (t == 0) {
        float tot = 0.f;
#pragma unroll
        for (int w = 0; w < 16; ++w) tot += ws[w];
        out[0] = tot / (float)NROW;
    }
}

extern "C" void kernel_launch(void* const* d_in, const int* in_sizes, int n_in,
                              void* d_out, int out_size) {
    const float* X = (const float*)d_in[0];   // inputs  [16384, 512] f32
    const float* P = (const float*)d_in[1];   // positive[16384, 512] f32
    float* out = (float*)d_out;

    cudaFuncSetAttribute(mma_topk_kernel,
                         cudaFuncAttributeMaxDynamicSharedMemorySize, SMEM_TOTAL);

    cvtsq_kernel<<<NROW, 128>>>(X);
    mma_topk_kernel<<<128, 160, SMEM_TOTAL>>>();
    rowloss_kernel<<<NROW / 8, 256>>>(X, P);
    reduce_kernel<<<1, 512>>>(out);
}

// round 6
// speedup vs baseline: 20.9086x; 1.2505x over previous
#include <cuda_runtime.h>
#include <cuda_bf16.h>
#include <math.h>
#include <float.h>
#include <stdint.h>

#define NROW 16384
#define DIM  512
#define MARGIN 2.0f
#define EPSV 1e-6f

// Arch-specific (sm_103a) feature gate: tcgen05/TMEM PTX only exists in the
// 'a' compilation pass. The plain compute_103/sm_103 pass gets a SIMT fallback.
#if defined(__CUDA_ARCH_FEAT_SM103_ALL) || (defined(__CUDA_ARCH_SPECIFIC__) && (__CUDA_ARCH_SPECIFIC__ == 1030))
#define HAS_TCGEN05 1
#else
#define HAS_TCGEN05 0
#endif

// ---- device scratch (no dynamic allocation allowed) ----
__device__ float g_sq[NROW];
__device__ int   g_neg[NROW];
__device__ float g_rowloss[NROW];
__device__ __align__(16) uint32_t g_xb[NROW * DIM / 2];   // bf16x2-packed inputs

// SMEM layout (dynamic), tcgen05 path
#define SMEM_TPTR  0
#define SMEM_MBAR0 8
#define SMEM_MBAR1 16
#define SMEM_SQS   32            // 4 slots x 256B
#define SMEM_B     2048          // 3 x 65536 (N=64 tile: 64 rows x 512 K bf16)
#define SMEM_TOTAL (2048 + 3 * 65536)

#define TMEM_A  0                // 256 cols: A 128x512 bf16
#define TMEM_D0 256              // 64 cols: D 128x64 f32
#define TMEM_D1 320

#define NTILE 256                // 16384 / 64 column tiles
#define THREADS 224              // w0=MMA, w1-4=epilogue, w5-6=loaders

#if HAS_TCGEN05
// ============================================================
// PTX helpers (sm_103a tcgen05 / mbarrier / cp.async)
// ============================================================
__device__ __forceinline__ uint32_t elect_one() {
    uint32_t p;
    asm volatile("{\n\t.reg .pred p;\n\telect.sync _|p, 0xFFFFFFFF;\n\tselp.b32 %0, 1, 0, p;\n\t}" : "=r"(p));
    return p;
}
#define TCGEN05_ALLOC(dst, n) \
    asm volatile("tcgen05.alloc.cta_group::1.sync.aligned.shared::cta.b32 [%0], %1;" :: "r"(dst), "r"(n) : "memory")
#define TCGEN05_DEALLOC(t, n) \
    asm volatile("tcgen05.dealloc.cta_group::1.sync.aligned.b32 %0, %1;" :: "r"(t), "r"(n))
#define TCGEN05_RELINQ() \
    asm volatile("tcgen05.relinquish_alloc_permit.cta_group::1.sync.aligned;")
#define TCGEN05_WAIT_ST() asm volatile("tcgen05.wait::st.sync.aligned;" ::: "memory")
#define TCGEN05_WAIT_LD() asm volatile("tcgen05.wait::ld.sync.aligned;" ::: "memory")
#define TCGEN05_FENCE_BEFORE() asm volatile("tcgen05.fence::before_thread_sync;" ::: "memory")
#define TCGEN05_FENCE_AFTER()  asm volatile("tcgen05.fence::after_thread_sync;" ::: "memory")
#define FENCE_PROXY_ASYNC() asm volatile("fence.proxy.async.shared::cta;" ::: "memory")
#define MBARRIER_INIT(m, c) \
    asm volatile("mbarrier.init.shared.b64 [%0], %1;" :: "r"(m), "r"(c) : "memory")
#define TCGEN05_COMMIT(m) \
    asm volatile("tcgen05.commit.cta_group::1.mbarrier::arrive::one.shared::cluster.b64 [%0];" :: "r"(m) : "memory")

#define MBARRIER_WAIT_PARITY(mbar_smem_addr, phase_parity) do { \
    uint32_t _mbar = (uint32_t)(mbar_smem_addr); \
    uint32_t _parity = (uint32_t)(phase_parity); \
    uint32_t _done; \
    asm volatile("{\n\t.reg .pred p;\n\t" \
        "mbarrier.try_wait.parity.acquire.cta.shared::cta.b64 p, [%1], %2;\n\t" \
        "selp.b32 %0, 1, 0, p;\n\t}" : "=r"(_done) : "r"(_mbar), "r"(_parity) : "memory"); \
    if (!_done) { \
        asm volatile("{\n\t.reg .pred P1;\n\t" \
            "WAIT_LOOP_%=:\n\t" \
            "mbarrier.try_wait.parity.acquire.cta.shared::cta.b64 P1, [%0], %1, 0x989680;\n\t" \
            "@P1 bra.uni WAIT_DONE_%=;\n\t" \
            "bra.uni WAIT_LOOP_%=;\n\t" \
            "WAIT_DONE_%=:\n\t}" :: "r"(_mbar), "r"(_parity) : "memory"); \
    } \
} while (0)

#define TCGEN05_ST_X32(tmem_addr, r) \
    asm volatile("tcgen05.st.sync.aligned.32x32b.x32.b32 [%0], " \
        "{%1, %2, %3, %4, %5, %6, %7, %8, %9, %10, %11, %12, %13, %14, %15, %16, " \
        "%17, %18, %19, %20, %21, %22, %23, %24, %25, %26, %27, %28, %29, %30, %31, %32};" \
        :: "r"(tmem_addr), \
           "r"((r)[0]),"r"((r)[1]),"r"((r)[2]),"r"((r)[3]),"r"((r)[4]),"r"((r)[5]),"r"((r)[6]),"r"((r)[7]), \
           "r"((r)[8]),"r"((r)[9]),"r"((r)[10]),"r"((r)[11]),"r"((r)[12]),"r"((r)[13]),"r"((r)[14]),"r"((r)[15]), \
           "r"((r)[16]),"r"((r)[17]),"r"((r)[18]),"r"((r)[19]),"r"((r)[20]),"r"((r)[21]),"r"((r)[22]),"r"((r)[23]), \
           "r"((r)[24]),"r"((r)[25]),"r"((r)[26]),"r"((r)[27]),"r"((r)[28]),"r"((r)[29]),"r"((r)[30]),"r"((r)[31]) \
        : "memory")

#define TCGEN05_LD_X32(r, tmem_addr) \
    asm volatile("tcgen05.ld.sync.aligned.32x32b.x32.b32 " \
        "{%0, %1, %2, %3, %4, %5, %6, %7, %8, %9, %10, %11, %12, %13, %14, %15, " \
        "%16, %17, %18, %19, %20, %21, %22, %23, %24, %25, %26, %27, %28, %29, %30, %31}, [%32];" \
        : "=r"((r)[0]),"=r"((r)[1]),"=r"((r)[2]),"=r"((r)[3]),"=r"((r)[4]),"=r"((r)[5]),"=r"((r)[6]),"=r"((r)[7]), \
          "=r"((r)[8]),"=r"((r)[9]),"=r"((r)[10]),"=r"((r)[11]),"=r"((r)[12]),"=r"((r)[13]),"=r"((r)[14]),"=r"((r)[15]), \
          "=r"((r)[16]),"=r"((r)[17]),"=r"((r)[18]),"=r"((r)[19]),"=r"((r)[20]),"=r"((r)[21]),"=r"((r)[22]),"=r"((r)[23]), \
          "=r"((r)[24]),"=r"((r)[25]),"=r"((r)[26]),"=r"((r)[27]),"=r"((r)[28]),"=r"((r)[29]),"=r"((r)[30]),"=r"((r)[31]) \
        : "r"(tmem_addr))

__device__ __forceinline__ void cp_async16(uint32_t dst, const void* src) {
    asm volatile("cp.async.cg.shared.global [%0], [%1], 16;" :: "r"(dst), "l"(src));
}
#define CP_COMMIT() asm volatile("cp.async.commit_group;" ::: "memory")
#define CP_WAIT0()  asm volatile("cp.async.wait_group 0;" ::: "memory")
#define CP_WAIT1()  asm volatile("cp.async.wait_group 1;" ::: "memory")
#define CP_WAIT2()  asm volatile("cp.async.wait_group 2;" ::: "memory")

// TS-mode bf16 MMA: A in TMEM, B via SMEM descriptor
__device__ __forceinline__ void mma_f16_ts(uint32_t d_tmem, uint32_t a_tmem,
                                           uint64_t b_desc, uint32_t idesc, bool acc) {
    uint32_t en = acc ? 1u : 0u;
    uint32_t z = 0u;
    asm volatile("{\n\t.reg .pred p;\n\tsetp.ne.u32 p, %5, 0;\n\t"
        "tcgen05.mma.cta_group::1.kind::f16 [%0], [%1], %2, %3, {%4, %4, %4, %4}, p;\n\t}"
        :: "r"(d_tmem), "r"(a_tmem), "l"(b_desc), "r"(idesc), "r"(z), "r"(en)
        : "memory");
}

// SW128 K-major SMEM descriptor (LBO=1, SBO=64)
__device__ __forceinline__ uint64_t make_desc(uint32_t addr) {
    return (uint64_t(2) << 61) | (uint64_t(1) << 46) | (uint64_t(64) << 32)
         | (uint64_t(1) << 16) | ((addr >> 4) & 0x3FFF);
}

// idesc: F32 accum, bf16 A/B, M=128 (8<<24), N=64 (8<<17)
#define MMA_IDESC ((8u << 24) | (8u << 17) | (1u << 10) | (1u << 7) | (1u << 4))
#endif  // HAS_TCGEN05

__device__ __forceinline__ uint32_t smem_u32(const void* p) {
    uint32_t a;
    asm("{ .reg .u64 t; cvta.to.shared.u64 t, %1; cvt.u32.u64 %0, t; }" : "=r"(a) : "l"(p));
    return a;
}

// ============================================================
// Kernel 0: fused fp32->bf16x2 convert + per-row squared norm.
// ============================================================
__global__ __launch_bounds__(128) void cvtsq_kernel(const float* __restrict__ X) {
    int row = blockIdx.x;
    int t = threadIdx.x;
    float4 v = *(const float4*)(X + (size_t)row * DIM + t * 4);
    uint32_t lo, hi;
    asm("cvt.rn.bf16x2.f32 %0, %1, %2;" : "=r"(lo) : "f"(v.y), "f"(v.x));
    asm("cvt.rn.bf16x2.f32 %0, %1, %2;" : "=r"(hi) : "f"(v.w), "f"(v.z));
    *(uint2*)(g_xb + (size_t)row * 256 + t * 2) = make_uint2(lo, hi);
    float s = v.x * v.x + v.y * v.y + v.z * v.z + v.w * v.w;
#pragma unroll
    for (int o = 16; o > 0; o >>= 1) s += __shfl_down_sync(0xffffffffu, s, o);
    __shared__ float ws[4];
    if ((t & 31) == 0) ws[t >> 5] = s;
    __syncthreads();
    if (t == 0) g_sq[row] = ws[0] + ws[1] + ws[2] + ws[3];
}

// ============================================================
// Kernel 1: warp-specialized tcgen05 bf16 GEMM + min-screened top-3.
// 128 CTAs x 224 threads:
//   w0    = MMA issuer (+sq prefetch, 2-tile slack)
//   w1-w4 = epilogue warps (one TMEM subpartition / 32 rows each):
//           wait mbar -> LDTM -> FMNMX min-screen -> rare ordered insert
//   w5-w6 = loader warps (cp.async B tile t+2 into 3-deep ring)
// key = sq[j] - 2*dot(i,j); ascending cols + strict < == jax ties.
// ============================================================
__global__ __launch_bounds__(THREADS, 1)
void mma_topk_kernel() {
    extern __shared__ char smem[];
    const uint32_t smem_base = smem_u32(smem);
    const int tid = threadIdx.x;
    const int rowBase = blockIdx.x * 128;

#if HAS_TCGEN05
    const int wid = tid >> 5;
    const int lane = tid & 31;
    const bool is_mma = (wid == 0);
    const bool is_epi = (wid >= 1 && wid <= 4);
    const int smsp = wid & 3;                    // epilogue subpartition
    const int row = smsp * 32 + lane;            // epilogue row / TMEM lane

    // ---- TMEM alloc + mbar init ----
    if (is_mma) {
        TCGEN05_ALLOC(smem_base + SMEM_TPTR, 512);
        TCGEN05_RELINQ();
    }
    if (tid == 0) {
        MBARRIER_INIT(smem_base + SMEM_MBAR0, 1);
        MBARRIER_INIT(smem_base + SMEM_MBAR1, 1);
    }
    __syncthreads();
    uint32_t tmem_base;
    asm volatile("ld.shared.b32 %0, [%1];" : "=r"(tmem_base) : "r"(smem_base + SMEM_TPTR));

    // ---- prologue ----
    if (is_epi) {
        // store A (this warp's 32 rows x 512 bf16) to TMEM
        const uint4* arow = (const uint4*)g_xb + (size_t)(rowBase + row) * (DIM / 8);
        uint32_t wo = (uint32_t)smsp << 21;
#pragma unroll
        for (int c8 = 0; c8 < 8; ++c8) {
            uint32_t r[32];
#pragma unroll
            for (int u = 0; u < 8; ++u) {
                uint4 v = arow[c8 * 8 + u];
                r[u * 4 + 0] = v.x; r[u * 4 + 1] = v.y;
                r[u * 4 + 2] = v.z; r[u * 4 + 3] = v.w;
            }
            TCGEN05_ST_X32(tmem_base + TMEM_A + c8 * 32 + wo, r);
        }
        TCGEN05_WAIT_ST();
        TCGEN05_FENCE_BEFORE();
    } else if (is_mma) {
        // sq tiles 0 and 1, as two separate groups (uniform group count)
        if (lane < 16)
            cp_async16(smem_base + SMEM_SQS + lane * 16, (const char*)g_sq + lane * 16);
        CP_COMMIT();
        if (lane < 16)
            cp_async16(smem_base + SMEM_SQS + 256 + lane * 16, (const char*)g_sq + 256 + lane * 16);
        CP_COMMIT();
    } else {
        // loaders: B tiles 0,1 as two groups
        const int lt = tid - 160;   // 0..63
#pragma unroll
        for (int pt = 0; pt < 2; ++pt) {
            const uint32_t bufo = SMEM_B + pt * 65536;
            const size_t colw = (size_t)pt * 64 * 256;
#pragma unroll 4
            for (int l = 0; l < 64; ++l) {
                int f = lt + l * 64;
                int s = f >> 9, w = f & 511, j = w >> 3, u = w & 7;
                uint32_t bo = (uint32_t)(j * 128 + u * 16);
                uint32_t sw = bo ^ ((bo >> 3) & 0x70);
                cp_async16(smem_base + bufo + s * 8192 + sw,
                           (const char*)g_xb + (colw + (size_t)j * 256 + s * 32 + u * 4) * 4);
            }
            CP_COMMIT();
        }
        CP_WAIT1();          // B tile 0 landed
        FENCE_PROXY_ASYNC();
    }
    __syncthreads();

    // per-epilogue-thread top-3 state
    float v0 = FLT_MAX, v1 = FLT_MAX, v2 = FLT_MAX;
    int   i0 = 0, i1 = 0, i2 = 0;

    int b_cur = 0;                 // t % 3
    int b_nxt2 = 2;                // (t+2) % 3

    for (int t = 0; t < NTILE; ++t) {
        if (is_mma) {
            // issue MMA(t) on buf[t%3] -> D[t&1], commit -> mbar[t&1]
            TCGEN05_FENCE_AFTER();
            if (elect_one()) {
                uint64_t bdesc = make_desc(smem_base + SMEM_B + b_cur * 65536);
                uint32_t dtm = tmem_base + ((t & 1) ? TMEM_D1 : TMEM_D0);
#pragma unroll
                for (int c = 0; c < 32; ++c) {
                    uint64_t bd = bdesc + (uint64_t)((c >> 2) * 512 + (c & 3) * 2);
                    mma_f16_ts(dtm, tmem_base + TMEM_A + c * 8, bd, MMA_IDESC, c > 0);
                }
                TCGEN05_COMMIT(smem_base + ((t & 1) ? SMEM_MBAR1 : SMEM_MBAR0));
            }
            // prefetch sq tile t+2 into slot (t+2)&3; 2-tile slack -> wait 2
            if (t + 2 < NTILE && lane < 16)
                cp_async16(smem_base + SMEM_SQS + ((t + 2) & 3) * 256 + lane * 16,
                           (const char*)g_sq + (size_t)(t + 2) * 256 + lane * 16);
            CP_COMMIT();
            CP_WAIT2();
        } else if (is_epi) {
            if (t >= 1) {
                uint32_t mb = smem_base + (((t - 1) & 1) ? SMEM_MBAR1 : SMEM_MBAR0);
                MBARRIER_WAIT_PARITY(mb, ((t - 1) >> 1) & 1);
                TCGEN05_FENCE_AFTER();

                const float* sqt = (const float*)(smem + SMEM_SQS + ((t - 1) & 3) * 256);
                const int colBase = (t - 1) * 64;
                const uint32_t dtm = tmem_base + (((t - 1) & 1) ? TMEM_D1 : TMEM_D0);
                uint32_t dr[64];
                TCGEN05_LD_X32(dr, dtm);
                TCGEN05_LD_X32(dr + 32, dtm + 32);
                TCGEN05_WAIT_LD();
#pragma unroll
                for (int g = 0; g < 4; ++g) {
                    float key[16];
#pragma unroll
                    for (int c = 0; c < 16; ++c)
                        key[c] = fmaf(-2.f, __uint_as_float(dr[g * 16 + c]), sqt[g * 16 + c]);
                    // branch-free min tree (depth 4)
                    float t8[8];
#pragma unroll
                    for (int c = 0; c < 8; ++c) t8[c] = fminf(key[c], key[c + 8]);
                    float t4a = fminf(t8[0], t8[4]), t4b = fminf(t8[1], t8[5]);
                    float t4c = fminf(t8[2], t8[6]), t4d = fminf(t8[3], t8[7]);
                    float mn = fminf(fminf(t4a, t4b), fminf(t4c, t4d));
                    if (mn < v2) {   // rare: exact ordered insert, ascending cols
#pragma unroll
                        for (int c = 0; c < 16; ++c) {
                            float k = key[c];
                            int col = colBase + g * 16 + c;
                            if (k < v2) {
                                if (k < v1) {
                                    v2 = v1; i2 = i1;
                                    if (k < v0) { v1 = v0; i1 = i0; v0 = k; i0 = col; }
                                    else        { v1 = k; i1 = col; }
                                } else { v2 = k; i2 = col; }
                            }
                        }
                    }
                }
                TCGEN05_FENCE_BEFORE();
            }
        } else {
            // loaders: WAR — buf[(t+2)%3] was last read by MMA(t-1)
            if (t >= 1) {
                uint32_t mb = smem_base + (((t - 1) & 1) ? SMEM_MBAR1 : SMEM_MBAR0);
                MBARRIER_WAIT_PARITY(mb, ((t - 1) >> 1) & 1);
            }
            if (t + 2 < NTILE) {
                const int lt = tid - 160;
                const uint32_t bufo = SMEM_B + b_nxt2 * 65536;
                const size_t colw = (size_t)(t + 2) * 64 * 256;
#pragma unroll 4
                for (int l = 0; l < 64; ++l) {
                    int f = lt + l * 64;
                    int s = f >> 9, w = f & 511, j = w >> 3, u = w & 7;
                    uint32_t bo = (uint32_t)(j * 128 + u * 16);
                    uint32_t sw = bo ^ ((bo >> 3) & 0x70);
                    cp_async16(smem_base + bufo + s * 8192 + sw,
                               (const char*)g_xb + (colw + (size_t)j * 256 + s * 32 + u * 4) * 4);
                }
            }
            CP_COMMIT();
            CP_WAIT1();          // B tile t+1 landed (issued last iteration)
            FENCE_PROXY_ASYNC();
        }
        __syncthreads();
        b_cur = (b_cur == 2) ? 0 : b_cur + 1;
        b_nxt2 = (b_nxt2 == 2) ? 0 : b_nxt2 + 1;
    }

    // ---- final epilogue: tile NTILE-1 ----
    if (is_epi) {
        uint32_t mb = smem_base + (((NTILE - 1) & 1) ? SMEM_MBAR1 : SMEM_MBAR0);
        MBARRIER_WAIT_PARITY(mb, ((NTILE - 1) >> 1) & 1);
        TCGEN05_FENCE_AFTER();
        const float* sqt = (const float*)(smem + SMEM_SQS + ((NTILE - 1) & 3) * 256);
        const int colBase = (NTILE - 1) * 64;
        const uint32_t dtm = tmem_base + (((NTILE - 1) & 1) ? TMEM_D1 : TMEM_D0);
        uint32_t dr[64];
        TCGEN05_LD_X32(dr, dtm);
        TCGEN05_LD_X32(dr + 32, dtm + 32);
        TCGEN05_WAIT_LD();
#pragma unroll
        for (int c = 0; c < 64; ++c) {
            float k = fmaf(-2.f, __uint_as_float(dr[c]), sqt[c]);
            int col = colBase + c;
            if (k < v2) {
                if (k < v1) {
                    v2 = v1; i2 = i1;
                    if (k < v0) { v1 = v0; i1 = i0; v0 = k; i0 = col; }
                    else        { v1 = k; i1 = col; }
                } else { v2 = k; i2 = col; }
            }
        }
        TCGEN05_FENCE_BEFORE();
        g_neg[rowBase + row] = i2;
    }

    __syncthreads();
    if (is_mma) TCGEN05_DEALLOC(tmem_base, 512);

#else  // ---------------- SIMT fallback (non-'a' pass) ----------------
    float* As = (float*)(smem);               // [16][64]
    float* Bs = (float*)(smem + 4096);        // [16][128]
    float* mv = (float*)(smem + 12288);       // [64][48]
    int*   mi = (int*)(smem + 36864);         // [64][48]
    const int tx = tid & 15, ty = tid >> 4;
    const bool act = (tid < 128);

    for (int half = 0; half < 2; ++half) {
        const int rh = rowBase + half * 64;
        float tv[8][3]; int tii[8][3];
#pragma unroll
        for (int i = 0; i < 8; ++i)
#pragma unroll
            for (int q = 0; q < 3; ++q) { tv[i][q] = FLT_MAX; tii[i][q] = 0x7fffffff; }

        for (int jt = 0; jt < NROW / 128; ++jt) {
            const int colBase = jt * 128;
            float c[8][8];
#pragma unroll
            for (int i = 0; i < 8; ++i)
#pragma unroll
                for (int j = 0; j < 8; ++j) c[i][j] = 0.f;

            for (int kt = 0; kt < DIM; kt += 16) {
                __syncthreads();
                if (act) {
#pragma unroll
                    for (int l = 0; l < 4; ++l) {
                        int f = tid + l * 128;
                        int r = f >> 3, u = f & 7;
                        uint32_t w = g_xb[(size_t)(rh + r) * 256 + kt / 2 + u];
                        __nv_bfloat162 b2 = *(__nv_bfloat162*)&w;
                        float2 f2 = __bfloat1622float2(b2);
                        As[(2 * u + 0) * 64 + r] = f2.x;
                        As[(2 * u + 1) * 64 + r] = f2.y;
                    }
#pragma unroll
                    for (int l = 0; l < 8; ++l) {
                        int f = tid + l * 128;
                        int r = f >> 3, u = f & 7;
                        uint32_t w = g_xb[(size_t)(colBase + r) * 256 + kt / 2 + u];
                        __nv_bfloat162 b2 = *(__nv_bfloat162*)&w;
                        float2 f2 = __bfloat1622float2(b2);
                        Bs[(2 * u + 0) * 128 + r] = f2.x;
                        Bs[(2 * u + 1) * 128 + r] = f2.y;
                    }
                }
                __syncthreads();
                if (act) {
#pragma unroll
                    for (int kk = 0; kk < 16; ++kk) {
                        float a[8], b[8];
#pragma unroll
                        for (int i = 0; i < 8; ++i) a[i] = As[kk * 64 + ty * 8 + i];
#pragma unroll
                        for (int j = 0; j < 8; ++j) b[j] = Bs[kk * 128 + tx * 8 + j];
#pragma unroll
                        for (int i = 0; i < 8; ++i)
#pragma unroll
                            for (int j = 0; j < 8; ++j) c[i][j] += a[i] * b[j];
                    }
                }
            }
            if (act) {
#pragma unroll
                for (int j = 0; j < 8; ++j) {
                    int col = colBase + tx * 8 + j;
                    float sqc = g_sq[col];
#pragma unroll
                    for (int i = 0; i < 8; ++i) {
                        float d2 = fmaf(-2.f, c[i][j], sqc);
                        bool b2c = (d2 < tv[i][2]) || (d2 == tv[i][2] && col < tii[i][2]);
                        if (b2c) {
                            bool b1c = (d2 < tv[i][1]) || (d2 == tv[i][1] && col < tii[i][1]);
                            bool b0c = (d2 < tv[i][0]) || (d2 == tv[i][0] && col < tii[i][0]);
                            if (b0c) {
                                tv[i][2] = tv[i][1]; tii[i][2] = tii[i][1];
                                tv[i][1] = tv[i][0]; tii[i][1] = tii[i][0];
                                tv[i][0] = d2;       tii[i][0] = col;
                            } else if (b1c) {
                                tv[i][2] = tv[i][1]; tii[i][2] = tii[i][1];
                                tv[i][1] = d2;       tii[i][1] = col;
                            } else { tv[i][2] = d2; tii[i][2] = col; }
                        }
                    }
                }
            }
        }

        __syncthreads();
        if (act) {
#pragma unroll
            for (int i = 0; i < 8; ++i)
#pragma unroll
                for (int q = 0; q < 3; ++q) {
                    mv[(ty * 8 + i) * 48 + tx * 3 + q] = tv[i][q];
                    mi[(ty * 8 + i) * 48 + tx * 3 + q] = tii[i][q];
                }
        }
        __syncthreads();
        if (tid < 64) {
            float w0 = FLT_MAX, w1 = FLT_MAX, w2 = FLT_MAX;
            int   j0 = 0x7fffffff, j1 = 0x7fffffff, j2 = 0x7fffffff;
            for (int cnd = 0; cnd < 48; ++cnd) {
                float d = mv[tid * 48 + cnd];
                int   ix = mi[tid * 48 + cnd];
                bool b2c = (d < w2) || (d == w2 && ix < j2);
                if (b2c) {
                    bool b1c = (d < w1) || (d == w1 && ix < j1);
                    bool b0c = (d < w0) || (d == w0 && ix < j0);
                    if (b0c)      { w2 = w1; j2 = j1; w1 = w0; j1 = j0; w0 = d; j0 = ix; }
                    else if (b1c) { w2 = w1; j2 = j1; w1 = d; j1 = ix; }
                    else          { w2 = d;  j2 = ix; }
                }
            }
            g_neg[rh + tid] = j2;
        }
        __syncthreads();
    }
#endif
}

// ============================================================
// Kernel 2: per-row triplet loss (one warp per row, fp32 exact)
// ============================================================
__global__ __launch_bounds__(256) void rowloss_kernel(const float* __restrict__ X,
                                                      const float* __restrict__ P) {
    int warp = threadIdx.x >> 5;
    int lane = threadIdx.x & 31;
    int row = blockIdx.x * 8 + warp;
    const float4* xr = (const float4*)(X + (size_t)row * DIM);
    const float4* pr = (const float4*)(P + (size_t)row * DIM);
    const float4* nr = (const float4*)(X + (size_t)g_neg[row] * DIM);
    float sap = 0.f, san = 0.f;
#pragma unroll
    for (int i = 0; i < 4; ++i) {
        float4 x = xr[lane + 32 * i];
        float4 p = pr[lane + 32 * i];
        float4 v = nr[lane + 32 * i];
        float d;
        d = x.x - p.x + EPSV; sap += d * d;
        d = x.y - p.y + EPSV; sap += d * d;
        d = x.z - p.z + EPSV; sap += d * d;
        d = x.w - p.w + EPSV; sap += d * d;
        d = x.x - v.x + EPSV; san += d * d;
        d = x.y - v.y + EPSV; san += d * d;
        d = x.z - v.z + EPSV; san += d * d;
        d = x.w - v.w + EPSV; san += d * d;
    }
#pragma unroll
    for (int o = 16; o > 0; o >>= 1) {
        sap += __shfl_down_sync(0xffffffffu, sap, o);
        san += __shfl_down_sync(0xffffffffu, san, o);
    }
    if (lane == 0)
        g_rowloss[row] = fmaxf(sqrtf(sap) - sqrtf(san) + MARGIN, 0.f);
}

// ============================================================
// Kernel 3: mean reduction -> d_out[0]
// ============================================================
__global__ __launch_bounds__(512) void reduce_kernel(float* __restrict__ out) {
    int t = threadIdx.x;
    float s = 0.f;
    for (int i = t; i < NROW; i += 512) s += g_rowloss[i];
#pragma unroll
    for (int o = 16; o > 0; o >>= 1) s += __shfl_down_sync(0xffffffffu, s, o);
    __shared__ float ws[16];
    if ((t & 31) == 0) ws[t >> 5] = s;
    __syncthreads();
    if (t == 0) {
        float tot = 0.f;
#pragma unroll
        for (int w = 0; w < 16; ++w) tot += ws[w];
        out[0] = tot / (float)NROW;
    }
}

extern "C" void kernel_launch(void* const* d_in, const int* in_sizes, int n_in,
                              void* d_out, int out_size) {
    const float* X = (const float*)d_in[0];   // inputs  [16384, 512] f32
    const float* P = (const float*)d_in[1];   // positive[16384, 512] f32
    float* out = (float*)d_out;

    cudaFuncSetAttribute(mma_topk_kernel,
                         cudaFuncAttributeMaxDynamicSharedMemorySize, SMEM_TOTAL);

    cvtsq_kernel<<<NROW, 128>>>(X);
    mma_topk_kernel<<<128, THREADS, SMEM_TOTAL>>>();
    rowloss_kernel<<<NROW / 8, 256>>>(X, P);
    reduce_kernel<<<1, 512>>>(out);
}

// round 8
// speedup vs baseline: 30.1394x; 1.4415x over previous
#include <cuda_runtime.h>
#include <cuda_bf16.h>
#include <math.h>
#include <float.h>
#include <stdint.h>

#define NROW 16384
#define DIM  512
#define MARGIN 2.0f
#define EPSV 1e-6f

// Arch-specific (sm_103a) feature gate: tcgen05/TMEM PTX only exists in the
// 'a' compilation pass. The plain compute_103/sm_103 pass gets a SIMT fallback.
#if defined(__CUDA_ARCH_FEAT_SM103_ALL) || (defined(__CUDA_ARCH_SPECIFIC__) && (__CUDA_ARCH_SPECIFIC__ == 1030))
#define HAS_TCGEN05 1
#else
#define HAS_TCGEN05 0
#endif

// ---- device scratch (no dynamic allocation allowed) ----
__device__ __align__(16) float g_sq[NROW];
__device__ int   g_neg[NROW];
__device__ float g_rowloss[NROW];
// bf16 inputs stored PRE-SWIZZLED as 256 column-tiles of 64KB each:
// tile t (rows t*64..t*64+63), 8 slabs of 8KB (64 elems of K each),
// within slab: byte bo = r*128 + (k&63)*2, stored at bo^((bo>>3)&0x70).
// A linear 64KB bulk copy reproduces the SW128 SMEM image exactly.
__device__ __align__(256) uint32_t g_xb[NROW * DIM / 2];

// SMEM layout (dynamic), tcgen05 path
#define SMEM_TPTR   0
#define SMEM_FULL0  8            // 3 mbarriers (B ring complete_tx)
#define SMEM_DONE0  32           // 2 mbarriers (MMA commit)
#define SMEM_DFREE0 48           // 2 mbarriers (epilogue done with D+sq)
#define SMEM_SQF0   64           // 4 mbarriers (sq ring complete_tx)
#define SMEM_SQS    1024         // 4 slots x 256B
#define SMEM_B      2048         // 3 x 65536
#define SMEM_TOTAL  (2048 + 3 * 65536)

#define TMEM_A  0                // 256 cols: A 128x512 bf16
#define TMEM_D0 256              // 64 cols: D 128x64 f32
#define TMEM_D1 320

#define NTILE 256                // 16384 / 64 column tiles
#define THREADS 160              // w0 = MMA + producer, w1-4 = epilogue

#if HAS_TCGEN05
// ============================================================
// PTX helpers (sm_103a tcgen05 / mbarrier / bulk-async)
// ============================================================
__device__ __forceinline__ uint32_t elect_one() {
    uint32_t p;
    asm volatile("{\n\t.reg .pred p;\n\telect.sync _|p, 0xFFFFFFFF;\n\tselp.b32 %0, 1, 0, p;\n\t}" : "=r"(p));
    return p;
}
#define TCGEN05_ALLOC(dst, n) \
    asm volatile("tcgen05.alloc.cta_group::1.sync.aligned.shared::cta.b32 [%0], %1;" :: "r"(dst), "r"(n) : "memory")
#define TCGEN05_DEALLOC(t, n) \
    asm volatile("tcgen05.dealloc.cta_group::1.sync.aligned.b32 %0, %1;" :: "r"(t), "r"(n))
#define TCGEN05_RELINQ() \
    asm volatile("tcgen05.relinquish_alloc_permit.cta_group::1.sync.aligned;")
#define TCGEN05_WAIT_ST() asm volatile("tcgen05.wait::st.sync.aligned;" ::: "memory")
#define TCGEN05_WAIT_LD() asm volatile("tcgen05.wait::ld.sync.aligned;" ::: "memory")
#define TCGEN05_FENCE_BEFORE() asm volatile("tcgen05.fence::before_thread_sync;" ::: "memory")
#define TCGEN05_FENCE_AFTER()  asm volatile("tcgen05.fence::after_thread_sync;" ::: "memory")
#define MBARRIER_INIT(m, c) \
    asm volatile("mbarrier.init.shared.b64 [%0], %1;" :: "r"(m), "r"(c) : "memory")
#define MBARRIER_ARRIVE(m) \
    asm volatile("mbarrier.arrive.release.cta.shared.b64 _, [%0];" :: "r"(m) : "memory")
#define MBARRIER_EXPECT_TX(m, b) \
    asm volatile("mbarrier.arrive.expect_tx.shared.b64 _, [%0], %1;" :: "r"(m), "r"(b) : "memory")
#define TCGEN05_COMMIT(m) \
    asm volatile("tcgen05.commit.cta_group::1.mbarrier::arrive::one.shared::cluster.b64 [%0];" :: "r"(m) : "memory")

#define MBARRIER_WAIT_PARITY(mbar_smem_addr, phase_parity) do { \
    uint32_t _mbar = (uint32_t)(mbar_smem_addr); \
    uint32_t _parity = (uint32_t)(phase_parity); \
    uint32_t _done; \
    asm volatile("{\n\t.reg .pred p;\n\t" \
        "mbarrier.try_wait.parity.acquire.cta.shared::cta.b64 p, [%1], %2;\n\t" \
        "selp.b32 %0, 1, 0, p;\n\t}" : "=r"(_done) : "r"(_mbar), "r"(_parity) : "memory"); \
    if (!_done) { \
        asm volatile("{\n\t.reg .pred P1;\n\t" \
            "WAIT_LOOP_%=:\n\t" \
            "mbarrier.try_wait.parity.acquire.cta.shared::cta.b64 P1, [%0], %1, 0x989680;\n\t" \
            "@P1 bra.uni WAIT_DONE_%=;\n\t" \
            "bra.uni WAIT_LOOP_%=;\n\t" \
            "WAIT_DONE_%=:\n\t}" :: "r"(_mbar), "r"(_parity) : "memory"); \
    } \
} while (0)

#define TCGEN05_ST_X32(tmem_addr, r) \
    asm volatile("tcgen05.st.sync.aligned.32x32b.x32.b32 [%0], " \
        "{%1, %2, %3, %4, %5, %6, %7, %8, %9, %10, %11, %12, %13, %14, %15, %16, " \
        "%17, %18, %19, %20, %21, %22, %23, %24, %25, %26, %27, %28, %29, %30, %31, %32};" \
        :: "r"(tmem_addr), \
           "r"((r)[0]),"r"((r)[1]),"r"((r)[2]),"r"((r)[3]),"r"((r)[4]),"r"((r)[5]),"r"((r)[6]),"r"((r)[7]), \
           "r"((r)[8]),"r"((r)[9]),"r"((r)[10]),"r"((r)[11]),"r"((r)[12]),"r"((r)[13]),"r"((r)[14]),"r"((r)[15]), \
           "r"((r)[16]),"r"((r)[17]),"r"((r)[18]),"r"((r)[19]),"r"((r)[20]),"r"((r)[21]),"r"((r)[22]),"r"((r)[23]), \
           "r"((r)[24]),"r"((r)[25]),"r"((r)[26]),"r"((r)[27]),"r"((r)[28]),"r"((r)[29]),"r"((r)[30]),"r"((r)[31]) \
        : "memory")

#define TCGEN05_LD_X32(r, tmem_addr) \
    asm volatile("tcgen05.ld.sync.aligned.32x32b.x32.b32 " \
        "{%0, %1, %2, %3, %4, %5, %6, %7, %8, %9, %10, %11, %12, %13, %14, %15, " \
        "%16, %17, %18, %19, %20, %21, %22, %23, %24, %25, %26, %27, %28, %29, %30, %31}, [%32];" \
        : "=r"((r)[0]),"=r"((r)[1]),"=r"((r)[2]),"=r"((r)[3]),"=r"((r)[4]),"=r"((r)[5]),"=r"((r)[6]),"=r"((r)[7]), \
          "=r"((r)[8]),"=r"((r)[9]),"=r"((r)[10]),"=r"((r)[11]),"=r"((r)[12]),"=r"((r)[13]),"=r"((r)[14]),"=r"((r)[15]), \
          "=r"((r)[16]),"=r"((r)[17]),"=r"((r)[18]),"=r"((r)[19]),"=r"((r)[20]),"=r"((r)[21]),"=r"((r)[22]),"=r"((r)[23]), \
          "=r"((r)[24]),"=r"((r)[25]),"=r"((r)[26]),"=r"((r)[27]),"=r"((r)[28]),"=r"((r)[29]),"=r"((r)[30]),"=r"((r)[31]) \
        : "r"(tmem_addr))

__device__ __forceinline__ void bulk_g2s(uint32_t dst, const void* src, uint32_t bytes, uint32_t mbar) {
    asm volatile("cp.async.bulk.shared::cta.global.mbarrier::complete_tx::bytes [%0], [%1], %2, [%3];"
                 :: "r"(dst), "l"(src), "r"(bytes), "r"(mbar) : "memory");
}

// TS-mode bf16 MMA: A in TMEM, B via SMEM descriptor
__device__ __forceinline__ void mma_f16_ts(uint32_t d_tmem, uint32_t a_tmem,
                                           uint64_t b_desc, uint32_t idesc, bool acc) {
    uint32_t en = acc ? 1u : 0u;
    uint32_t z = 0u;
    asm volatile("{\n\t.reg .pred p;\n\tsetp.ne.u32 p, %5, 0;\n\t"
        "tcgen05.mma.cta_group::1.kind::f16 [%0], [%1], %2, %3, {%4, %4, %4, %4}, p;\n\t}"
        :: "r"(d_tmem), "r"(a_tmem), "l"(b_desc), "r"(idesc), "r"(z), "r"(en)
        : "memory");
}

// SW128 K-major SMEM descriptor (LBO=1, SBO=64)
__device__ __forceinline__ uint64_t make_desc(uint32_t addr) {
    return (uint64_t(2) << 61) | (uint64_t(1) << 46) | (uint64_t(64) << 32)
         | (uint64_t(1) << 16) | ((addr >> 4) & 0x3FFF);
}

// idesc: F32 accum, bf16 A/B, M=128 (8<<24), N=64 (8<<17)
#define MMA_IDESC ((8u << 24) | (8u << 17) | (1u << 10) | (1u << 7) | (1u << 4))
#endif  // HAS_TCGEN05

__device__ __forceinline__ uint32_t smem_u32(const void* p) {
    uint32_t a;
    asm("{ .reg .u64 t; cvta.to.shared.u64 t, %1; cvt.u32.u64 %0, t; }" : "=r"(a) : "l"(p));
    return a;
}

// ============================================================
// Kernel 0: fused fp32->bf16x2 convert (to pre-swizzled layout)
// + per-row squared norm.
// ============================================================
__global__ __launch_bounds__(128) void cvtsq_kernel(const float* __restrict__ X) {
    int row = blockIdx.x;
    int t = threadIdx.x;
    float4 v = *(const float4*)(X + (size_t)row * DIM + t * 4);
    uint32_t lo, hi;
    asm("cvt.rn.bf16x2.f32 %0, %1, %2;" : "=r"(lo) : "f"(v.y), "f"(v.x));
    asm("cvt.rn.bf16x2.f32 %0, %1, %2;" : "=r"(hi) : "f"(v.w), "f"(v.z));
    int tile = row >> 6, r = row & 63;
    int k = t * 4;                                  // element index in [0,512)
    uint32_t bo = (uint32_t)(r * 128 + (k & 63) * 2);
    uint32_t sw = bo ^ ((bo >> 3) & 0x70);
    *(uint2*)((char*)g_xb + (size_t)tile * 65536 + (size_t)(k >> 6) * 8192 + sw)
        = make_uint2(lo, hi);
    float s = v.x * v.x + v.y * v.y + v.z * v.z + v.w * v.w;
#pragma unroll
    for (int o = 16; o > 0; o >>= 1) s += __shfl_down_sync(0xffffffffu, s, o);
    __shared__ float ws[4];
    if ((t & 31) == 0) ws[t >> 5] = s;
    __syncthreads();
    if (t == 0) g_sq[row] = ws[0] + ws[1] + ws[2] + ws[3];
}

// ============================================================
// Kernel 1: fully-async tcgen05 bf16 GEMM + min-screened top-3.
// 128 CTAs x 160 threads, NO per-tile __syncthreads.
//   w0    = producer+MMA. Per tile u: wait dfree(u-2) [D+sq WAR],
//           wait full(u%3) [B landed], issue MMA(u)->D[u&1],
//           commit->done[u&1], wait done(u-1) [B ring WAR], then
//           bulk-load B(u+2)->buf[(u+2)%3] and sq(u+2)->slot[(u+2)&3].
//   w1-w4 = epilogue. Per tile u: wait done[u&1], wait sqfull[u&3],
//           LDTM D[u&1], compute keys + min-screen top-3, THEN arrive
//           dfree[u&1] (so dfree == "done with D AND sq").
// key = sq[j] - 2*dot(i,j); ascending cols + strict < == jax ties.
// ============================================================
__global__ __launch_bounds__(THREADS, 1)
void mma_topk_kernel() {
    extern __shared__ char smem[];
    const uint32_t smem_base = smem_u32(smem);
    const int tid = threadIdx.x;
    const int rowBase = blockIdx.x * 128;
    const char* xb = (const char*)g_xb;

#if HAS_TCGEN05
    const int wid = tid >> 5;
    const int lane = tid & 31;
    const bool is_mma = (wid == 0);
    const int smsp = wid & 3;                    // epilogue subpartition
    const int row = smsp * 32 + lane;            // epilogue row / TMEM lane

    // ---- TMEM alloc + mbar init ----
    if (is_mma) {
        TCGEN05_ALLOC(smem_base + SMEM_TPTR, 512);
        TCGEN05_RELINQ();
    }
    if (tid == 0) {
#pragma unroll
        for (int s = 0; s < 3; ++s) MBARRIER_INIT(smem_base + SMEM_FULL0 + s * 8, 1);
        MBARRIER_INIT(smem_base + SMEM_DONE0, 1);
        MBARRIER_INIT(smem_base + SMEM_DONE0 + 8, 1);
        MBARRIER_INIT(smem_base + SMEM_DFREE0, 4);
        MBARRIER_INIT(smem_base + SMEM_DFREE0 + 8, 4);
#pragma unroll
        for (int s = 0; s < 4; ++s) MBARRIER_INIT(smem_base + SMEM_SQF0 + s * 8, 1);
    }
    __syncthreads();
    uint32_t tmem_base;
    asm volatile("ld.shared.b32 %0, [%1];" : "=r"(tmem_base) : "r"(smem_base + SMEM_TPTR));

    // ---- prologue ----
    if (!is_mma) {
        // store A (this warp's 32 rows x 512 bf16) to TMEM, reading the
        // pre-swizzled g_xb image (de-swizzle per 16B granule).
        const int R = rowBase + row;
        const int tt = R >> 6, r = R & 63;
        const char* tbase = xb + (size_t)tt * 65536;
        uint32_t wo = (uint32_t)smsp << 21;
#pragma unroll
        for (int c8 = 0; c8 < 8; ++c8) {
            uint32_t rg[32];
#pragma unroll
            for (int u = 0; u < 8; ++u) {
                int g = c8 * 8 + u;
                uint32_t bo = (uint32_t)(r * 128 + (g & 7) * 16);
                uint32_t sw = bo ^ ((bo >> 3) & 0x70);
                uint4 v = *(const uint4*)(tbase + (size_t)(g >> 3) * 8192 + sw);
                rg[u * 4 + 0] = v.x; rg[u * 4 + 1] = v.y;
                rg[u * 4 + 2] = v.z; rg[u * 4 + 3] = v.w;
            }
            TCGEN05_ST_X32(tmem_base + TMEM_A + c8 * 32 + wo, rg);
        }
        TCGEN05_WAIT_ST();
        TCGEN05_FENCE_BEFORE();
    } else {
        // issue bulk loads for tiles 0 and 1 (B 64KB; sq 256B separate ring)
        if (elect_one()) {
#pragma unroll
            for (int pt = 0; pt < 2; ++pt) {
                uint32_t fb = smem_base + SMEM_FULL0 + pt * 8;
                MBARRIER_EXPECT_TX(fb, 65536);
                bulk_g2s(smem_base + SMEM_B + pt * 65536, xb + (size_t)pt * 65536, 65536, fb);
                uint32_t qb = smem_base + SMEM_SQF0 + pt * 8;
                MBARRIER_EXPECT_TX(qb, 256);
                bulk_g2s(smem_base + SMEM_SQS + pt * 256, (const char*)g_sq + pt * 256, 256, qb);
            }
        }
    }
    __syncthreads();   // A in TMEM visible to MMA warp

    if (is_mma) {
        TCGEN05_FENCE_AFTER();
        for (int u = 0; u < NTILE; ++u) {
            const int b = u & 1;
            // D WAR + sq-slot WAR: epilogue fully done with tile u-2
            if (u >= 2) {
                MBARRIER_WAIT_PARITY(smem_base + SMEM_DFREE0 + b * 8, ((u - 2) >> 1) & 1);
                TCGEN05_FENCE_AFTER();
            }
            // B data for tile u landed
            MBARRIER_WAIT_PARITY(smem_base + SMEM_FULL0 + (u % 3) * 8, (u / 3) & 1);
            if (elect_one()) {
                uint64_t bdesc = make_desc(smem_base + SMEM_B + (u % 3) * 65536);
                uint32_t dtm = tmem_base + (b ? TMEM_D1 : TMEM_D0);
#pragma unroll
                for (int c = 0; c < 32; ++c) {
                    uint64_t bd = bdesc + (uint64_t)((c >> 2) * 512 + (c & 3) * 2);
                    mma_f16_ts(dtm, tmem_base + TMEM_A + c * 8, bd, MMA_IDESC, c > 0);
                }
                TCGEN05_COMMIT(smem_base + SMEM_DONE0 + b * 8);
            }
            // recycle: B(u+2) -> buf[(u+2)%3] (last read by MMA(u-1));
            //          sq(u+2) -> slot[(u+2)&3] (last read by epi(u-2), via dfree)
            if (u + 2 < NTILE) {
                if (u >= 1)
                    MBARRIER_WAIT_PARITY(smem_base + SMEM_DONE0 + ((u - 1) & 1) * 8,
                                         ((u - 1) >> 1) & 1);
                if (elect_one()) {
                    int s2 = (u + 2) % 3;
                    uint32_t fb = smem_base + SMEM_FULL0 + s2 * 8;
                    MBARRIER_EXPECT_TX(fb, 65536);
                    bulk_g2s(smem_base + SMEM_B + s2 * 65536,
                             xb + (size_t)(u + 2) * 65536, 65536, fb);
                    int q2 = (u + 2) & 3;
                    uint32_t qb = smem_base + SMEM_SQF0 + q2 * 8;
                    MBARRIER_EXPECT_TX(qb, 256);
                    bulk_g2s(smem_base + SMEM_SQS + q2 * 256,
                             (const char*)g_sq + (size_t)(u + 2) * 256, 256, qb);
                }
            }
        }
    } else {
        // epilogue warps: per-thread top-3 over all tiles
        float v0 = FLT_MAX, v1 = FLT_MAX, v2 = FLT_MAX;
        int   i0 = 0, i1 = 0, i2 = 0;
        for (int u = 0; u < NTILE; ++u) {
            const int b = u & 1;
            MBARRIER_WAIT_PARITY(smem_base + SMEM_DONE0 + b * 8, (u >> 1) & 1);
            TCGEN05_FENCE_AFTER();
            // sq tile u landed (normally long since complete)
            MBARRIER_WAIT_PARITY(smem_base + SMEM_SQF0 + (u & 3) * 8, (u >> 2) & 1);
            const float* sqt = (const float*)(smem + SMEM_SQS + (u & 3) * 256);
            const int colBase = u * 64;
            const uint32_t dtm = tmem_base + (b ? TMEM_D1 : TMEM_D0);
            uint32_t dr[64];
            TCGEN05_LD_X32(dr, dtm);
            TCGEN05_LD_X32(dr + 32, dtm + 32);
            TCGEN05_WAIT_LD();
#pragma unroll
            for (int g = 0; g < 4; ++g) {
                float key[16];
#pragma unroll
                for (int c = 0; c < 16; ++c)
                    key[c] = fmaf(-2.f, __uint_as_float(dr[g * 16 + c]), sqt[g * 16 + c]);
                float t8[8];
#pragma unroll
                for (int c = 0; c < 8; ++c) t8[c] = fminf(key[c], key[c + 8]);
                float t4a = fminf(t8[0], t8[4]), t4b = fminf(t8[1], t8[5]);
                float t4c = fminf(t8[2], t8[6]), t4d = fminf(t8[3], t8[7]);
                float mn = fminf(fminf(t4a, t4b), fminf(t4c, t4d));
                if (mn < v2) {   // rare: exact ordered insert, ascending cols
#pragma unroll
                    for (int c = 0; c < 16; ++c) {
                        float k = key[c];
                        int col = colBase + g * 16 + c;
                        if (k < v2) {
                            if (k < v1) {
                                v2 = v1; i2 = i1;
                                if (k < v0) { v1 = v0; i1 = i0; v0 = k; i0 = col; }
                                else        { v1 = k; i1 = col; }
                            } else { v2 = k; i2 = col; }
                        }
                    }
                }
            }
            // now fully done with D[b] and sq slot: release to producer
            TCGEN05_FENCE_BEFORE();
            if (lane == 0) MBARRIER_ARRIVE(smem_base + SMEM_DFREE0 + b * 8);
        }
        g_neg[rowBase + row] = i2;
    }

    __syncthreads();
    if (is_mma) TCGEN05_DEALLOC(tmem_base, 512);

#else  // ---------------- SIMT fallback (non-'a' pass) ----------------
    // Reads the pre-swizzled g_xb layout via per-4B de-swizzle.
    float* As = (float*)(smem);               // [16][64]
    float* Bs = (float*)(smem + 4096);        // [16][128]
    float* mv = (float*)(smem + 12288);       // [64][48]
    int*   mi = (int*)(smem + 36864);         // [64][48]
    const int tx = tid & 15, ty = tid >> 4;
    const bool act = (tid < 128);

    for (int half = 0; half < 2; ++half) {
        const int rh = rowBase + half * 64;
        float tv[8][3]; int tii[8][3];
#pragma unroll
        for (int i = 0; i < 8; ++i)
#pragma unroll
            for (int q = 0; q < 3; ++q) { tv[i][q] = FLT_MAX; tii[i][q] = 0x7fffffff; }

        for (int jt = 0; jt < NROW / 128; ++jt) {
            const int colBase = jt * 128;
            float c[8][8];
#pragma unroll
            for (int i = 0; i < 8; ++i)
#pragma unroll
                for (int j = 0; j < 8; ++j) c[i][j] = 0.f;

            for (int kt = 0; kt < DIM; kt += 16) {
                __syncthreads();
                if (act) {
#pragma unroll
                    for (int l = 0; l < 4; ++l) {
                        int f = tid + l * 128;
                        int r = f >> 3, uu = f & 7;
                        int R = rh + r, kk = kt + 2 * uu;
                        uint32_t bo = (uint32_t)((R & 63) * 128 + (kk & 63) * 2);
                        uint32_t sw = bo ^ ((bo >> 3) & 0x70);
                        uint32_t w = *(const uint32_t*)(xb + (size_t)(R >> 6) * 65536
                                                        + (size_t)(kk >> 6) * 8192 + sw);
                        __nv_bfloat162 b2 = *(__nv_bfloat162*)&w;
                        float2 f2 = __bfloat1622float2(b2);
                        As[(2 * uu + 0) * 64 + r] = f2.x;
                        As[(2 * uu + 1) * 64 + r] = f2.y;
                    }
#pragma unroll
                    for (int l = 0; l < 8; ++l) {
                        int f = tid + l * 128;
                        int r = f >> 3, uu = f & 7;
                        int R = colBase + r, kk = kt + 2 * uu;
                        uint32_t bo = (uint32_t)((R & 63) * 128 + (kk & 63) * 2);
                        uint32_t sw = bo ^ ((bo >> 3) & 0x70);
                        uint32_t w = *(const uint32_t*)(xb + (size_t)(R >> 6) * 65536
                                                        + (size_t)(kk >> 6) * 8192 + sw);
                        __nv_bfloat162 b2 = *(__nv_bfloat162*)&w;
                        float2 f2 = __bfloat1622float2(b2);
                        Bs[(2 * uu + 0) * 128 + r] = f2.x;
                        Bs[(2 * uu + 1) * 128 + r] = f2.y;
                    }
                }
                __syncthreads();
                if (act) {
#pragma unroll
                    for (int kk = 0; kk < 16; ++kk) {
                        float a[8], b[8];
#pragma unroll
                        for (int i = 0; i < 8; ++i) a[i] = As[kk * 64 + ty * 8 + i];
#pragma unroll
                        for (int j = 0; j < 8; ++j) b[j] = Bs[kk * 128 + tx * 8 + j];
#pragma unroll
                        for (int i = 0; i < 8; ++i)
#pragma unroll
                            for (int j = 0; j < 8; ++j) c[i][j] += a[i] * b[j];
                    }
                }
            }
            if (act) {
#pragma unroll
                for (int j = 0; j < 8; ++j) {
                    int col = colBase + tx * 8 + j;
                    float sqc = g_sq[col];
#pragma unroll
                    for (int i = 0; i < 8; ++i) {
                        float d2 = fmaf(-2.f, c[i][j], sqc);
                        bool b2c = (d2 < tv[i][2]) || (d2 == tv[i][2] && col < tii[i][2]);
                        if (b2c) {
                            bool b1c = (d2 < tv[i][1]) || (d2 == tv[i][1] && col < tii[i][1]);
                            bool b0c = (d2 < tv[i][0]) || (d2 == tv[i][0] && col < tii[i][0]);
                            if (b0c) {
                                tv[i][2] = tv[i][1]; tii[i][2] = tii[i][1];
                                tv[i][1] = tv[i][0]; tii[i][1] = tii[i][0];
                                tv[i][0] = d2;       tii[i][0] = col;
                            } else if (b1c) {
                                tv[i][2] = tv[i][1]; tii[i][2] = tii[i][1];
                                tv[i][1] = d2;       tii[i][1] = col;
                            } else { tv[i][2] = d2; tii[i][2] = col; }
                        }
                    }
                }
            }
        }

        __syncthreads();
        if (act) {
#pragma unroll
            for (int i = 0; i < 8; ++i)
#pragma unroll
                for (int q = 0; q < 3; ++q) {
                    mv[(ty * 8 + i) * 48 + tx * 3 + q] = tv[i][q];
                    mi[(ty * 8 + i) * 48 + tx * 3 + q] = tii[i][q];
                }
        }
        __syncthreads();
        if (tid < 64) {
            float w0 = FLT_MAX, w1 = FLT_MAX, w2 = FLT_MAX;
            int   j0 = 0x7fffffff, j1 = 0x7fffffff, j2 = 0x7fffffff;
            for (int cnd = 0; cnd < 48; ++cnd) {
                float d = mv[tid * 48 + cnd];
                int   ix = mi[tid * 48 + cnd];
                bool b2c = (d < w2) || (d == w2 && ix < j2);
                if (b2c) {
                    bool b1c = (d < w1) || (d == w1 && ix < j1);
                    bool b0c = (d < w0) || (d == w0 && ix < j0);
                    if (b0c)      { w2 = w1; j2 = j1; w1 = w0; j1 = j0; w0 = d; j0 = ix; }
                    else if (b1c) { w2 = w1; j2 = j1; w1 = d; j1 = ix; }
                    else          { w2 = d;  j2 = ix; }
                }
            }
            g_neg[rh + tid] = j2;
        }
        __syncthreads();
    }
#endif
}

// ============================================================
// Kernel 2: per-row triplet loss (one warp per row, fp32 exact)
// ============================================================
__global__ __launch_bounds__(256) void rowloss_kernel(const float* __restrict__ X,
                                                      const float* __restrict__ P) {
    int warp = threadIdx.x >> 5;
    int lane = threadIdx.x & 31;
    int row = blockIdx.x * 8 + warp;
    const float4* xr = (const float4*)(X + (size_t)row * DIM);
    const float4* pr = (const float4*)(P + (size_t)row * DIM);
    const float4* nr = (const float4*)(X + (size_t)g_neg[row] * DIM);
    float sap = 0.f, san = 0.f;
#pragma unroll
    for (int i = 0; i < 4; ++i) {
        float4 x = xr[lane + 32 * i];
        float4 p = pr[lane + 32 * i];
        float4 v = nr[lane + 32 * i];
        float d;
        d = x.x - p.x + EPSV; sap += d * d;
        d = x.y - p.y + EPSV; sap += d * d;
        d = x.z - p.z + EPSV; sap += d * d;
        d = x.w - p.w + EPSV; sap += d * d;
        d = x.x - v.x + EPSV; san += d * d;
        d = x.y - v.y + EPSV; san += d * d;
        d = x.z - v.z + EPSV; san += d * d;
        d = x.w - v.w + EPSV; san += d * d;
    }
#pragma unroll
    for (int o = 16; o > 0; o >>= 1) {
        sap += __shfl_down_sync(0xffffffffu, sap, o);
        san += __shfl_down_sync(0xffffffffu, san, o);
    }
    if (lane == 0)
        g_rowloss[row] = fmaxf(sqrtf(sap) - sqrtf(san) + MARGIN, 0.f);
}

// ============================================================
// Kernel 3: mean reduction -> d_out[0]
// ============================================================
__global__ __launch_bounds__(512) void reduce_kernel(float* __restrict__ out) {
    int t = threadIdx.x;
    float s = 0.f;
    for (int i = t; i < NROW; i += 512) s += g_rowloss[i];
#pragma unroll
    for (int o = 16; o > 0; o >>= 1) s += __shfl_down_sync(0xffffffffu, s, o);
    __shared__ float ws[16];
    if ((t & 31) == 0) ws[t >> 5] = s;
    __syncthreads();
    if (t == 0) {
        float tot = 0.f;
#pragma unroll
        for (int w = 0; w < 16; ++w) tot += ws[w];
        out[0] = tot / (float)NROW;
    }
}

extern "C" void kernel_launch(void* const* d_in, const int* in_sizes, int n_in,
                              void* d_out, int out_size) {
    const float* X = (const float*)d_in[0];   // inputs  [16384, 512] f32
    const float* P = (const float*)d_in[1];   // positive[16384, 512] f32
    float* out = (float*)d_out;

    cudaFuncSetAttribute(mma_topk_kernel,
                         cudaFuncAttributeMaxDynamicSharedMemorySize, SMEM_TOTAL);

    cvtsq_kernel<<<NROW, 128>>>(X);
    mma_topk_kernel<<<128, THREADS, SMEM_TOTAL>>>();
    rowloss_kernel<<<NROW / 8, 256>>>(X, P);
    reduce_kernel<<<1, 512>>>(out);
}